// round 3
// baseline (speedup 1.0000x reference)
#include <cuda_runtime.h>
#include <math.h>

#define MAXN 100000
#define MAXE 1600000
typedef unsigned long long ull;

// packed f32x2 helpers (FFMA2/FADD2 — ptxas never emits these from plain C++)
__device__ __forceinline__ ull ffma2(ull a, ull b, ull c) {
    ull d; asm("fma.rn.f32x2 %0,%1,%2,%3;" : "=l"(d) : "l"(a), "l"(b), "l"(c)); return d;
}
__device__ __forceinline__ ull fadd2(ull a, ull b) {
    ull d; asm("add.rn.f32x2 %0,%1,%2;" : "=l"(d) : "l"(a), "l"(b)); return d;
}
__device__ __forceinline__ ull pack2(float x) {
    ull d; unsigned u = __float_as_uint(x);
    asm("mov.b64 %0,{%1,%1};" : "=l"(d) : "r"(u)); return d;
}
__device__ __forceinline__ float2 unpack2(ull v) {
    unsigned lo, hi; asm("mov.b64 {%0,%1},%2;" : "=r"(lo), "=r"(hi) : "l"(v));
    return make_float2(__uint_as_float(lo), __uint_as_float(hi));
}

// ---------------- scratch ----------------
__device__ int   g_indeg[MAXN];
__device__ int   g_rowstart[MAXN];
__device__ int   g_cursor[MAXN];
__device__ int   g_bsum[256];
__device__ float g_dis[MAXN];
__device__ int   g_csr[MAXE];              // src only (weights folded into row prescale)
__device__ float g_h0[(size_t)MAXN * 64];  // dis[row]-prescaled x@W1
__device__ float g_h [(size_t)MAXN * 64];  // normalized hidden
__device__ float g_gg[(size_t)MAXN * 64];  // dis-prescaled, (mu_j,ls_j) interleaved
__device__ float g_z [(size_t)MAXN * 32];

// ---------------- graph preprocessing ----------------
__global__ void init_kernel(int n) {
    int i = blockIdx.x * blockDim.x + threadIdx.x;
    if (i < n) g_indeg[i] = 0;
}

__global__ void hist_kernel(const int* __restrict__ dst, int E) {
    int e = blockIdx.x * blockDim.x + threadIdx.x;
    if (e < E) atomicAdd(&g_indeg[dst[e]], 1);
}

__global__ void scan1_kernel(int n) {
    __shared__ int sm[1024];
    int t = threadIdx.x;
    int i = blockIdx.x * 1024 + t;
    int v = (i < n) ? g_indeg[i] : 0;
    if (i < n) g_dis[i] = rsqrtf((float)(v + 1));   // fused dis
    sm[t] = v;
    __syncthreads();
#pragma unroll
    for (int o = 1; o < 1024; o <<= 1) {
        int tv = (t >= o) ? sm[t - o] : 0;
        __syncthreads();
        sm[t] += tv;
        __syncthreads();
    }
    if (i < n) g_rowstart[i] = sm[t] - v;
    if (t == 1023) g_bsum[blockIdx.x] = sm[1023];
}

__global__ void scan2_kernel(int nb) {
    __shared__ int sm[256];
    int t = threadIdx.x;
    int v = (t < nb) ? g_bsum[t] : 0;
    sm[t] = v;
    __syncthreads();
#pragma unroll
    for (int o = 1; o < 256; o <<= 1) {
        int tv = (t >= o) ? sm[t - o] : 0;
        __syncthreads();
        sm[t] += tv;
        __syncthreads();
    }
    if (t < nb) g_bsum[t] = sm[t] - v;
}

__global__ void scan3_kernel(int n) {
    int i = blockIdx.x * blockDim.x + threadIdx.x;
    if (i < n) {
        int v = g_rowstart[i] + g_bsum[i >> 10];
        g_rowstart[i] = v;
        g_cursor[i]   = v;
    }
}

__global__ void fill_kernel(const int* __restrict__ src, const int* __restrict__ dst, int E) {
    int e = blockIdx.x * blockDim.x + threadIdx.x;
    if (e < E) {
        int p = atomicAdd(&g_cursor[dst[e]], 1);
        g_csr[p] = src[e];
    }
}

// ---------------- GEMM 1: g_h0 = dis[row] * (x[N,128] @ W1[128,64]) ----------------
__global__ void __launch_bounds__(256) gemm1_kernel(const float* __restrict__ x,
                                                    const float* __restrict__ W, int n) {
    __shared__ float ws[128 * 64];
    __shared__ float xsT[128 * 33];
    int tid = threadIdx.x;
    // copy W (row-major [128][64]) straight in, float4
    for (int i = tid; i < 128 * 16; i += 256)
        ((float4*)ws)[i] = ((const float4*)W)[i];
    int row0 = blockIdx.x * 32;
    for (int i = tid; i < 4096; i += 256) {
        int r = i >> 7, k = i & 127;
        int row = row0 + r;
        xsT[k * 33 + r] = (row < n) ? x[(size_t)row * 128 + k] : 0.f;  // conflict-free (pad 33)
    }
    __syncthreads();
    int lane = tid & 31, wrp = tid >> 5;
    int r  = wrp * 4 + (lane >> 3);
    int jt = lane & 7;
    ull a0 = 0, a1 = 0, a2 = 0, a3 = 0;
#pragma unroll 8
    for (int k = 0; k < 128; k++) {
        ull xx = pack2(xsT[k * 33 + r]);
        ulonglong2 wA = *(const ulonglong2*)(ws + k * 64 + 8 * jt);
        ulonglong2 wB = *(const ulonglong2*)(ws + k * 64 + 8 * jt + 4);
        a0 = ffma2(xx, wA.x, a0); a1 = ffma2(xx, wA.y, a1);
        a2 = ffma2(xx, wB.x, a2); a3 = ffma2(xx, wB.y, a3);
    }
    int row = row0 + r;
    if (row < n) {
        ull dd = pack2(g_dis[row]);                 // prescale rows by dis[row]
        a0 = ffma2(dd, a0, 0); a1 = ffma2(dd, a1, 0);
        a2 = ffma2(dd, a2, 0); a3 = ffma2(dd, a3, 0);
        ull* o = (ull*)(g_h0 + (size_t)row * 64 + jt * 8);
        o[0] = a0; o[1] = a1; o[2] = a2; o[3] = a3;
    }
}

// ---------------- GEMM 2: g_gg = dis[row] * (h[N,64] @ interleave(Wmu,Wls)) ----------------
__global__ void __launch_bounds__(256) gemm2_kernel(const float* __restrict__ Wmu,
                                                    const float* __restrict__ Wls, int n) {
    __shared__ float ws[64 * 64];
    __shared__ float xsT[64 * 33];
    int tid = threadIdx.x;
    for (int i = tid; i < 64 * 64; i += 256) {
        int k = i >> 6, j = i & 63;
        // interleaved column jn: even=mu_j, odd=ls_j
        float v = (j & 1) ? Wls[k * 32 + (j >> 1)] : Wmu[k * 32 + (j >> 1)];
        ws[k * 64 + j] = v;
    }
    int row0 = blockIdx.x * 32;
    for (int i = tid; i < 2048; i += 256) {
        int r = i >> 6, k = i & 63;
        int row = row0 + r;
        xsT[k * 33 + r] = (row < n) ? g_h[(size_t)row * 64 + k] : 0.f;
    }
    __syncthreads();
    int lane = tid & 31, wrp = tid >> 5;
    int r  = wrp * 4 + (lane >> 3);
    int jt = lane & 7;
    ull a0 = 0, a1 = 0, a2 = 0, a3 = 0;
#pragma unroll 8
    for (int k = 0; k < 64; k++) {
        ull xx = pack2(xsT[k * 33 + r]);
        ulonglong2 wA = *(const ulonglong2*)(ws + k * 64 + 8 * jt);
        ulonglong2 wB = *(const ulonglong2*)(ws + k * 64 + 8 * jt + 4);
        a0 = ffma2(xx, wA.x, a0); a1 = ffma2(xx, wA.y, a1);
        a2 = ffma2(xx, wB.x, a2); a3 = ffma2(xx, wB.y, a3);
    }
    int row = row0 + r;
    if (row < n) {
        ull dd = pack2(g_dis[row]);
        a0 = ffma2(dd, a0, 0); a1 = ffma2(dd, a1, 0);
        a2 = ffma2(dd, a2, 0); a3 = ffma2(dd, a3, 0);
        ull* o = (ull*)(g_gg + (size_t)row * 64 + jt * 8);
        o[0] = a0; o[1] = a1; o[2] = a2; o[3] = a3;
    }
}

// ---------------- Conv1: warp/node, unroll-8 gather, packed adds ----------------
__global__ void __launch_bounds__(256) conv1_kernel(const float* __restrict__ b1, int n) {
    int node = blockIdx.x * 8 + (threadIdx.x >> 5);
    int t    = threadIdx.x & 31;
    if (node >= n) return;
    int st  = g_rowstart[node];
    int cnt = g_indeg[node];
    const int* cs = g_csr + st;
    const float* hb = g_h0 + 2 * t;
    ull acc0 = 0, acc1 = 0;
    int e = 0;
    for (; e + 8 <= cnt; e += 8) {
        int s0 = cs[e], s1 = cs[e+1], s2 = cs[e+2], s3 = cs[e+3];
        int s4 = cs[e+4], s5 = cs[e+5], s6 = cs[e+6], s7 = cs[e+7];
        ull v0 = *(const ull*)(hb + (size_t)s0 * 64);
        ull v1 = *(const ull*)(hb + (size_t)s1 * 64);
        ull v2 = *(const ull*)(hb + (size_t)s2 * 64);
        ull v3 = *(const ull*)(hb + (size_t)s3 * 64);
        ull v4 = *(const ull*)(hb + (size_t)s4 * 64);
        ull v5 = *(const ull*)(hb + (size_t)s5 * 64);
        ull v6 = *(const ull*)(hb + (size_t)s6 * 64);
        ull v7 = *(const ull*)(hb + (size_t)s7 * 64);
        acc0 = fadd2(acc0, v0); acc1 = fadd2(acc1, v1);
        acc0 = fadd2(acc0, v2); acc1 = fadd2(acc1, v3);
        acc0 = fadd2(acc0, v4); acc1 = fadd2(acc1, v5);
        acc0 = fadd2(acc0, v6); acc1 = fadd2(acc1, v7);
    }
    for (; e < cnt; e++) {
        ull v = *(const ull*)(hb + (size_t)cs[e] * 64);
        acc0 = fadd2(acc0, v);
    }
    ull self = *(const ull*)(hb + (size_t)node * 64);
    float2 s = unpack2(fadd2(fadd2(acc0, acc1), self));
    float di = g_dis[node];
    float2 bb = *(const float2*)(b1 + 2 * t);
    float vx = fmaxf(fmaf(di, s.x, bb.x), 0.f);
    float vy = fmaxf(fmaf(di, s.y, bb.y), 0.f);
    float ss = vx * vx + vy * vy;
#pragma unroll
    for (int o = 16; o > 0; o >>= 1) ss += __shfl_xor_sync(0xffffffffu, ss, o);
    float scale = 1.0f / fmaxf(sqrtf(ss), 1e-12f);
    *(float2*)(g_h + (size_t)node * 64 + 2 * t) = make_float2(vx * scale, vy * scale);
}

// ---------------- Conv2 + reparametrize: warp/node ----------------
__global__ void __launch_bounds__(256) conv2_kernel(const float* __restrict__ bmu,
                                                    const float* __restrict__ bls,
                                                    const float* __restrict__ eps,
                                                    float* __restrict__ out_mu,
                                                    float* __restrict__ out_ls, int n) {
    int node = blockIdx.x * 8 + (threadIdx.x >> 5);
    int t    = threadIdx.x & 31;
    if (node >= n) return;
    int st  = g_rowstart[node];
    int cnt = g_indeg[node];
    const int* cs = g_csr + st;
    const float* gb = g_gg + 2 * t;
    ull acc0 = 0, acc1 = 0;
    int e = 0;
    for (; e + 8 <= cnt; e += 8) {
        int s0 = cs[e], s1 = cs[e+1], s2 = cs[e+2], s3 = cs[e+3];
        int s4 = cs[e+4], s5 = cs[e+5], s6 = cs[e+6], s7 = cs[e+7];
        ull v0 = *(const ull*)(gb + (size_t)s0 * 64);
        ull v1 = *(const ull*)(gb + (size_t)s1 * 64);
        ull v2 = *(const ull*)(gb + (size_t)s2 * 64);
        ull v3 = *(const ull*)(gb + (size_t)s3 * 64);
        ull v4 = *(const ull*)(gb + (size_t)s4 * 64);
        ull v5 = *(const ull*)(gb + (size_t)s5 * 64);
        ull v6 = *(const ull*)(gb + (size_t)s6 * 64);
        ull v7 = *(const ull*)(gb + (size_t)s7 * 64);
        acc0 = fadd2(acc0, v0); acc1 = fadd2(acc1, v1);
        acc0 = fadd2(acc0, v2); acc1 = fadd2(acc1, v3);
        acc0 = fadd2(acc0, v4); acc1 = fadd2(acc1, v5);
        acc0 = fadd2(acc0, v6); acc1 = fadd2(acc1, v7);
    }
    for (; e < cnt; e++) {
        ull v = *(const ull*)(gb + (size_t)cs[e] * 64);
        acc0 = fadd2(acc0, v);
    }
    ull self = *(const ull*)(gb + (size_t)node * 64);
    float2 s = unpack2(fadd2(fadd2(acc0, acc1), self));
    float di = g_dis[node];
    float mu = fmaf(di, s.x, bmu[t]);
    float ls = fmaf(di, s.y, bls[t]);
    size_t oi = (size_t)node * 32 + t;
    out_mu[oi] = mu;
    out_ls[oi] = ls;
    float lc = fminf(fmaxf(ls, -10.f), 10.f);
    g_z[oi] = fmaf(eps[oi], expf(lc), mu);
}

// ---------------- decode: 8 lanes/edge ----------------
__global__ void __launch_bounds__(256) decode_kernel(const int* __restrict__ src,
                                                     const int* __restrict__ dst,
                                                     float* __restrict__ out, int E) {
    int gid = blockIdx.x * 256 + threadIdx.x;
    int e   = gid >> 3;
    int sub = gid & 7;
    if (e >= E) return;
    int s = src[e], d = dst[e];
    float4 a = *(const float4*)(g_z + (size_t)s * 32 + sub * 4);
    float4 b = *(const float4*)(g_z + (size_t)d * 32 + sub * 4);
    float p = a.x * b.x + a.y * b.y + a.z * b.z + a.w * b.w;
    p += __shfl_xor_sync(0xffffffffu, p, 1);
    p += __shfl_xor_sync(0xffffffffu, p, 2);
    p += __shfl_xor_sync(0xffffffffu, p, 4);
    if (sub == 0) out[e] = 1.0f / (1.0f + expf(-p));
}

// ---------------- launch ----------------
extern "C" void kernel_launch(void* const* d_in, const int* in_sizes, int n_in,
                              void* d_out, int out_size) {
    const float* x   = (const float*)d_in[0];
    const int*   ei  = (const int*)  d_in[1];
    const float* eps = (const float*)d_in[2];
    const float* W1  = (const float*)d_in[3];
    const float* b1  = (const float*)d_in[4];
    const float* Wmu = (const float*)d_in[5];
    const float* bmu = (const float*)d_in[6];
    const float* Wls = (const float*)d_in[7];
    const float* bls = (const float*)d_in[8];

    int n = in_sizes[0] / 128;
    int E = in_sizes[1] / 2;
    const int* src = ei;
    const int* dst = ei + E;

    float* out     = (float*)d_out;
    float* out_adj = out;
    float* out_mu  = out + E;
    float* out_ls  = out + E + (size_t)n * 32;

    init_kernel<<<(n + 255) / 256, 256>>>(n);
    hist_kernel<<<(E + 255) / 256, 256>>>(dst, E);
    int nb = (n + 1023) / 1024;
    scan1_kernel<<<nb, 1024>>>(n);
    scan2_kernel<<<1, 256>>>(nb);
    scan3_kernel<<<(n + 255) / 256, 256>>>(n);
    fill_kernel<<<(E + 255) / 256, 256>>>(src, dst, E);

    gemm1_kernel<<<(n + 31) / 32, 256>>>(x, W1, n);
    conv1_kernel<<<(n + 7) / 8, 256>>>(b1, n);
    gemm2_kernel<<<(n + 31) / 32, 256>>>(Wmu, Wls, n);
    conv2_kernel<<<(n + 7) / 8, 256>>>(bmu, bls, eps, out_mu, out_ls, n);
    decode_kernel<<<((size_t)E * 8 + 255) / 256, 256>>>(src, dst, out_adj, E);
}

// round 4
// speedup vs baseline: 1.2610x; 1.2610x over previous
#include <cuda_runtime.h>
#include <math.h>

#define MAXN 100000
#define MAXE 1600000

// ---------------- scratch ----------------
__device__ int   g_indeg[MAXN];
__device__ int   g_rowstart[MAXN];
__device__ int   g_cursor[MAXN];
__device__ int   g_bsum[256];
__device__ float g_dis[MAXN];
__device__ int   g_csr[MAXE];              // src only (weights folded into row prescale)
__device__ float g_h0[(size_t)MAXN * 64];  // dis[row]-prescaled x@W1
__device__ float g_h [(size_t)MAXN * 64];  // normalized hidden
__device__ float g_gg[(size_t)MAXN * 64];  // dis-prescaled, (mu_j,ls_j) interleaved
__device__ float g_z [(size_t)MAXN * 32];

// ---------------- graph preprocessing ----------------
__global__ void init_kernel(int n) {
    int i = blockIdx.x * blockDim.x + threadIdx.x;
    if (i < n) g_indeg[i] = 0;
}

__global__ void hist_kernel(const int* __restrict__ dst, int E) {
    int e = blockIdx.x * blockDim.x + threadIdx.x;
    if (e < E) atomicAdd(&g_indeg[dst[e]], 1);
}

__global__ void scan1_kernel(int n) {
    __shared__ int sm[1024];
    int t = threadIdx.x;
    int i = blockIdx.x * 1024 + t;
    int v = (i < n) ? g_indeg[i] : 0;
    if (i < n) g_dis[i] = rsqrtf((float)(v + 1));   // fused dis
    sm[t] = v;
    __syncthreads();
#pragma unroll
    for (int o = 1; o < 1024; o <<= 1) {
        int tv = (t >= o) ? sm[t - o] : 0;
        __syncthreads();
        sm[t] += tv;
        __syncthreads();
    }
    if (i < n) g_rowstart[i] = sm[t] - v;
    if (t == 1023) g_bsum[blockIdx.x] = sm[1023];
}

__global__ void scan2_kernel(int nb) {
    __shared__ int sm[256];
    int t = threadIdx.x;
    int v = (t < nb) ? g_bsum[t] : 0;
    sm[t] = v;
    __syncthreads();
#pragma unroll
    for (int o = 1; o < 256; o <<= 1) {
        int tv = (t >= o) ? sm[t - o] : 0;
        __syncthreads();
        sm[t] += tv;
        __syncthreads();
    }
    if (t < nb) g_bsum[t] = sm[t] - v;
}

__global__ void scan3_kernel(int n) {
    int i = blockIdx.x * blockDim.x + threadIdx.x;
    if (i < n) {
        int v = g_rowstart[i] + g_bsum[i >> 10];
        g_rowstart[i] = v;
        g_cursor[i]   = v;
    }
}

__global__ void fill_kernel(const int* __restrict__ src, const int* __restrict__ dst, int E) {
    int e = blockIdx.x * blockDim.x + threadIdx.x;
    if (e < E) {
        int p = atomicAdd(&g_cursor[dst[e]], 1);
        g_csr[p] = src[e];
    }
}

// ---------------- GEMM 1: g_h0 = dis[row] * (x[N,128] @ W1[128,64]) ----------------
__global__ void __launch_bounds__(256) gemm1_kernel(const float* __restrict__ x,
                                                    const float* __restrict__ W, int n) {
    __shared__ float wsa[128 * 32];
    __shared__ float wsb[128 * 32];
    __shared__ float xsT[128 * 33];     // pad 33: conflict-free transpose fill + read
    int tid = threadIdx.x;
    for (int i = tid; i < 128 * 64; i += 256) {
        int k = i >> 6, j = i & 63;
        float v = W[i];
        int jt = j >> 3, c = j & 7;
        if (c < 4) wsa[k * 32 + jt * 4 + c] = v;
        else       wsb[k * 32 + jt * 4 + (c - 4)] = v;
    }
    int row0 = blockIdx.x * 32;
    for (int i = tid; i < 4096; i += 256) {
        int r = i >> 7, k = i & 127;
        int row = row0 + r;
        xsT[k * 33 + r] = (row < n) ? x[(size_t)row * 128 + k] : 0.f;
    }
    __syncthreads();
    int lane = tid & 31, wrp = tid >> 5;
    int r  = wrp * 4 + (lane >> 3);
    int jt = lane & 7;
    float acc[8];
#pragma unroll
    for (int i = 0; i < 8; i++) acc[i] = 0.f;
    const float4* wa = (const float4*)wsa + jt;
    const float4* wb = (const float4*)wsb + jt;
#pragma unroll 8
    for (int k = 0; k < 128; k++) {
        float xf = xsT[k * 33 + r];
        float4 a = wa[k * 8];
        float4 b = wb[k * 8];
        acc[0] = fmaf(xf, a.x, acc[0]); acc[1] = fmaf(xf, a.y, acc[1]);
        acc[2] = fmaf(xf, a.z, acc[2]); acc[3] = fmaf(xf, a.w, acc[3]);
        acc[4] = fmaf(xf, b.x, acc[4]); acc[5] = fmaf(xf, b.y, acc[5]);
        acc[6] = fmaf(xf, b.z, acc[6]); acc[7] = fmaf(xf, b.w, acc[7]);
    }
    int row = row0 + r;
    if (row < n) {
        float di = g_dis[row];                       // prescale by dis[row]
        float4* o = (float4*)(g_h0 + (size_t)row * 64 + jt * 8);
        o[0] = make_float4(di*acc[0], di*acc[1], di*acc[2], di*acc[3]);
        o[1] = make_float4(di*acc[4], di*acc[5], di*acc[6], di*acc[7]);
    }
}

// ---------------- GEMM 2: g_gg = dis[row] * (h[N,64] @ interleave(Wmu,Wls)) ----------------
__global__ void __launch_bounds__(256) gemm2_kernel(const float* __restrict__ Wmu,
                                                    const float* __restrict__ Wls, int n) {
    __shared__ float wsa[64 * 32];
    __shared__ float wsb[64 * 32];
    __shared__ float xsT[64 * 33];
    int tid = threadIdx.x;
    for (int i = tid; i < 64 * 64; i += 256) {
        int k = i >> 6, j = i & 63;
        // interleaved output column jn: even=mu_(j'), odd=ls_(j')
        float v = (j < 32) ? Wmu[k * 32 + j] : Wls[k * 32 + (j - 32)];
        int jn = (j < 32) ? (2 * j) : (2 * (j - 32) + 1);
        int jt = jn >> 3, c = jn & 7;
        if (c < 4) wsa[k * 32 + jt * 4 + c] = v;
        else       wsb[k * 32 + jt * 4 + (c - 4)] = v;
    }
    int row0 = blockIdx.x * 32;
    for (int i = tid; i < 2048; i += 256) {
        int r = i >> 6, k = i & 63;
        int row = row0 + r;
        xsT[k * 33 + r] = (row < n) ? g_h[(size_t)row * 64 + k] : 0.f;
    }
    __syncthreads();
    int lane = tid & 31, wrp = tid >> 5;
    int r  = wrp * 4 + (lane >> 3);
    int jt = lane & 7;
    float acc[8];
#pragma unroll
    for (int i = 0; i < 8; i++) acc[i] = 0.f;
    const float4* wa = (const float4*)wsa + jt;
    const float4* wb = (const float4*)wsb + jt;
#pragma unroll 8
    for (int k = 0; k < 64; k++) {
        float xf = xsT[k * 33 + r];
        float4 a = wa[k * 8];
        float4 b = wb[k * 8];
        acc[0] = fmaf(xf, a.x, acc[0]); acc[1] = fmaf(xf, a.y, acc[1]);
        acc[2] = fmaf(xf, a.z, acc[2]); acc[3] = fmaf(xf, a.w, acc[3]);
        acc[4] = fmaf(xf, b.x, acc[4]); acc[5] = fmaf(xf, b.y, acc[5]);
        acc[6] = fmaf(xf, b.z, acc[6]); acc[7] = fmaf(xf, b.w, acc[7]);
    }
    int row = row0 + r;
    if (row < n) {
        float di = g_dis[row];
        float4* o = (float4*)(g_gg + (size_t)row * 64 + jt * 8);
        o[0] = make_float4(di*acc[0], di*acc[1], di*acc[2], di*acc[3]);
        o[1] = make_float4(di*acc[4], di*acc[5], di*acc[6], di*acc[7]);
    }
}

// ---------------- Conv1: warp/node, unroll-8 gather, plain float2 math ----------------
__global__ void __launch_bounds__(256) conv1_kernel(const float* __restrict__ b1, int n) {
    int node = blockIdx.x * 8 + (threadIdx.x >> 5);
    int t    = threadIdx.x & 31;
    if (node >= n) return;
    int st  = g_rowstart[node];
    int cnt = g_indeg[node];
    const int* cs = g_csr + st;
    const float* hb = g_h0 + 2 * t;
    float a0x = 0.f, a0y = 0.f, a1x = 0.f, a1y = 0.f;
    int e = 0;
    for (; e + 8 <= cnt; e += 8) {
        int s0 = cs[e], s1 = cs[e+1], s2 = cs[e+2], s3 = cs[e+3];
        int s4 = cs[e+4], s5 = cs[e+5], s6 = cs[e+6], s7 = cs[e+7];
        float2 v0 = *(const float2*)(hb + (size_t)s0 * 64);
        float2 v1 = *(const float2*)(hb + (size_t)s1 * 64);
        float2 v2 = *(const float2*)(hb + (size_t)s2 * 64);
        float2 v3 = *(const float2*)(hb + (size_t)s3 * 64);
        float2 v4 = *(const float2*)(hb + (size_t)s4 * 64);
        float2 v5 = *(const float2*)(hb + (size_t)s5 * 64);
        float2 v6 = *(const float2*)(hb + (size_t)s6 * 64);
        float2 v7 = *(const float2*)(hb + (size_t)s7 * 64);
        a0x += v0.x; a0y += v0.y; a1x += v1.x; a1y += v1.y;
        a0x += v2.x; a0y += v2.y; a1x += v3.x; a1y += v3.y;
        a0x += v4.x; a0y += v4.y; a1x += v5.x; a1y += v5.y;
        a0x += v6.x; a0y += v6.y; a1x += v7.x; a1y += v7.y;
    }
    for (; e < cnt; e++) {
        float2 v = *(const float2*)(hb + (size_t)cs[e] * 64);
        a0x += v.x; a0y += v.y;
    }
    float2 self = *(const float2*)(hb + (size_t)node * 64);
    float sx = a0x + a1x + self.x;
    float sy = a0y + a1y + self.y;
    float di = g_dis[node];
    float2 bb = *(const float2*)(b1 + 2 * t);
    float vx = fmaxf(fmaf(di, sx, bb.x), 0.f);
    float vy = fmaxf(fmaf(di, sy, bb.y), 0.f);
    float ss = vx * vx + vy * vy;
#pragma unroll
    for (int o = 16; o > 0; o >>= 1) ss += __shfl_xor_sync(0xffffffffu, ss, o);
    float scale = 1.0f / fmaxf(sqrtf(ss), 1e-12f);
    *(float2*)(g_h + (size_t)node * 64 + 2 * t) = make_float2(vx * scale, vy * scale);
}

// ---------------- Conv2 + reparametrize: warp/node ----------------
__global__ void __launch_bounds__(256) conv2_kernel(const float* __restrict__ bmu,
                                                    const float* __restrict__ bls,
                                                    const float* __restrict__ eps,
                                                    float* __restrict__ out_mu,
                                                    float* __restrict__ out_ls, int n) {
    int node = blockIdx.x * 8 + (threadIdx.x >> 5);
    int t    = threadIdx.x & 31;
    if (node >= n) return;
    int st  = g_rowstart[node];
    int cnt = g_indeg[node];
    const int* cs = g_csr + st;
    const float* gb = g_gg + 2 * t;
    float a0x = 0.f, a0y = 0.f, a1x = 0.f, a1y = 0.f;
    int e = 0;
    for (; e + 8 <= cnt; e += 8) {
        int s0 = cs[e], s1 = cs[e+1], s2 = cs[e+2], s3 = cs[e+3];
        int s4 = cs[e+4], s5 = cs[e+5], s6 = cs[e+6], s7 = cs[e+7];
        float2 v0 = *(const float2*)(gb + (size_t)s0 * 64);
        float2 v1 = *(const float2*)(gb + (size_t)s1 * 64);
        float2 v2 = *(const float2*)(gb + (size_t)s2 * 64);
        float2 v3 = *(const float2*)(gb + (size_t)s3 * 64);
        float2 v4 = *(const float2*)(gb + (size_t)s4 * 64);
        float2 v5 = *(const float2*)(gb + (size_t)s5 * 64);
        float2 v6 = *(const float2*)(gb + (size_t)s6 * 64);
        float2 v7 = *(const float2*)(gb + (size_t)s7 * 64);
        a0x += v0.x; a0y += v0.y; a1x += v1.x; a1y += v1.y;
        a0x += v2.x; a0y += v2.y; a1x += v3.x; a1y += v3.y;
        a0x += v4.x; a0y += v4.y; a1x += v5.x; a1y += v5.y;
        a0x += v6.x; a0y += v6.y; a1x += v7.x; a1y += v7.y;
    }
    for (; e < cnt; e++) {
        float2 v = *(const float2*)(gb + (size_t)cs[e] * 64);
        a0x += v.x; a0y += v.y;
    }
    float2 self = *(const float2*)(gb + (size_t)node * 64);
    float sx = a0x + a1x + self.x;
    float sy = a0y + a1y + self.y;
    float di = g_dis[node];
    float mu = fmaf(di, sx, bmu[t]);
    float ls = fmaf(di, sy, bls[t]);
    size_t oi = (size_t)node * 32 + t;
    out_mu[oi] = mu;
    out_ls[oi] = ls;
    float lc = fminf(fmaxf(ls, -10.f), 10.f);
    g_z[oi] = fmaf(eps[oi], __expf(lc), mu);
}

// ---------------- decode: 8 lanes/edge ----------------
__global__ void __launch_bounds__(256) decode_kernel(const int* __restrict__ src,
                                                     const int* __restrict__ dst,
                                                     float* __restrict__ out, int E) {
    int gid = blockIdx.x * 256 + threadIdx.x;
    int e   = gid >> 3;
    int sub = gid & 7;
    if (e >= E) return;
    int s = src[e], d = dst[e];
    float4 a = *(const float4*)(g_z + (size_t)s * 32 + sub * 4);
    float4 b = *(const float4*)(g_z + (size_t)d * 32 + sub * 4);
    float p = a.x * b.x + a.y * b.y + a.z * b.z + a.w * b.w;
    p += __shfl_xor_sync(0xffffffffu, p, 1);
    p += __shfl_xor_sync(0xffffffffu, p, 2);
    p += __shfl_xor_sync(0xffffffffu, p, 4);
    if (sub == 0) out[e] = 1.0f / (1.0f + __expf(-p));
}

// ---------------- launch ----------------
extern "C" void kernel_launch(void* const* d_in, const int* in_sizes, int n_in,
                              void* d_out, int out_size) {
    const float* x   = (const float*)d_in[0];
    const int*   ei  = (const int*)  d_in[1];
    const float* eps = (const float*)d_in[2];
    const float* W1  = (const float*)d_in[3];
    const float* b1  = (const float*)d_in[4];
    const float* Wmu = (const float*)d_in[5];
    const float* bmu = (const float*)d_in[6];
    const float* Wls = (const float*)d_in[7];
    const float* bls = (const float*)d_in[8];

    int n = in_sizes[0] / 128;
    int E = in_sizes[1] / 2;
    const int* src = ei;
    const int* dst = ei + E;

    float* out     = (float*)d_out;
    float* out_adj = out;
    float* out_mu  = out + E;
    float* out_ls  = out + E + (size_t)n * 32;

    init_kernel<<<(n + 255) / 256, 256>>>(n);
    hist_kernel<<<(E + 255) / 256, 256>>>(dst, E);
    int nb = (n + 1023) / 1024;
    scan1_kernel<<<nb, 1024>>>(n);
    scan2_kernel<<<1, 256>>>(nb);
    scan3_kernel<<<(n + 255) / 256, 256>>>(n);
    fill_kernel<<<(E + 255) / 256, 256>>>(src, dst, E);

    gemm1_kernel<<<(n + 31) / 32, 256>>>(x, W1, n);
    conv1_kernel<<<(n + 7) / 8, 256>>>(b1, n);
    gemm2_kernel<<<(n + 31) / 32, 256>>>(Wmu, Wls, n);
    conv2_kernel<<<(n + 7) / 8, 256>>>(bmu, bls, eps, out_mu, out_ls, n);
    decode_kernel<<<((size_t)E * 8 + 255) / 256, 256>>>(src, dst, out_adj, E);
}

// round 5
// speedup vs baseline: 1.3143x; 1.0422x over previous
#include <cuda_runtime.h>
#include <math.h>

#define MAXN 100000
#define MAXE 1600000

// ---------------- scratch ----------------
__device__ int   g_indeg[MAXN];
__device__ int   g_rowstart[MAXN];
__device__ int   g_cursor[MAXN];
__device__ int   g_bsum[256];
__device__ float g_dis[MAXN];
__device__ int   g_csr[MAXE];              // src only (weights folded into row prescale)
__device__ float g_h0[(size_t)MAXN * 64];  // dis[row]-prescaled x@W1
__device__ float g_h [(size_t)MAXN * 64];  // normalized hidden
__device__ float g_gg[(size_t)MAXN * 64];  // dis-prescaled, (mu_j,ls_j) interleaved
__device__ float g_z [(size_t)MAXN * 32];

// ---------------- graph preprocessing ----------------
__global__ void init_kernel(int n) {
    int i = blockIdx.x * blockDim.x + threadIdx.x;
    if (i < n) g_indeg[i] = 0;
}

__global__ void hist_kernel(const int* __restrict__ dst, int E) {
    int e = blockIdx.x * blockDim.x + threadIdx.x;
    if (e < E) atomicAdd(&g_indeg[dst[e]], 1);
}

__global__ void dis_kernel(int n) {
    int i = blockIdx.x * blockDim.x + threadIdx.x;
    if (i < n) g_dis[i] = rsqrtf((float)(g_indeg[i] + 1));
}

__global__ void scan1_kernel(int n) {
    __shared__ int sm[1024];
    int t = threadIdx.x;
    int i = blockIdx.x * 1024 + t;
    int v = (i < n) ? g_indeg[i] : 0;
    sm[t] = v;
    __syncthreads();
#pragma unroll
    for (int o = 1; o < 1024; o <<= 1) {
        int tv = (t >= o) ? sm[t - o] : 0;
        __syncthreads();
        sm[t] += tv;
        __syncthreads();
    }
    if (i < n) g_rowstart[i] = sm[t] - v;
    if (t == 1023) g_bsum[blockIdx.x] = sm[1023];
}

__global__ void scan2_kernel(int nb) {
    __shared__ int sm[256];
    int t = threadIdx.x;
    int v = (t < nb) ? g_bsum[t] : 0;
    sm[t] = v;
    __syncthreads();
#pragma unroll
    for (int o = 1; o < 256; o <<= 1) {
        int tv = (t >= o) ? sm[t - o] : 0;
        __syncthreads();
        sm[t] += tv;
        __syncthreads();
    }
    if (t < nb) g_bsum[t] = sm[t] - v;
}

__global__ void scan3_kernel(int n) {
    int i = blockIdx.x * blockDim.x + threadIdx.x;
    if (i < n) {
        int v = g_rowstart[i] + g_bsum[i >> 10];
        g_rowstart[i] = v;
        g_cursor[i]   = v;
    }
}

__global__ void fill_kernel(const int* __restrict__ src, const int* __restrict__ dst, int E) {
    int e = blockIdx.x * blockDim.x + threadIdx.x;
    if (e < E) {
        int p = atomicAdd(&g_cursor[dst[e]], 1);
        g_csr[p] = src[e];
    }
}

// ---------------- GEMM 1: g_h0 = dis[row] * (x[N,128] @ W1[128,64]) ----------------
__global__ void __launch_bounds__(256) gemm1_kernel(const float* __restrict__ x,
                                                    const float* __restrict__ W, int n) {
    __shared__ float wsa[128 * 32];
    __shared__ float wsb[128 * 32];
    __shared__ float xsT[128 * 33];     // pad 33: conflict-free transpose fill + read
    int tid = threadIdx.x;
    for (int i = tid; i < 128 * 64; i += 256) {
        int k = i >> 6, j = i & 63;
        float v = W[i];
        int jt = j >> 3, c = j & 7;
        if (c < 4) wsa[k * 32 + jt * 4 + c] = v;
        else       wsb[k * 32 + jt * 4 + (c - 4)] = v;
    }
    int row0 = blockIdx.x * 32;
    for (int i = tid; i < 4096; i += 256) {
        int r = i >> 7, k = i & 127;
        int row = row0 + r;
        xsT[k * 33 + r] = (row < n) ? x[(size_t)row * 128 + k] : 0.f;
    }
    __syncthreads();
    int lane = tid & 31, wrp = tid >> 5;
    int r  = wrp * 4 + (lane >> 3);
    int jt = lane & 7;
    float acc[8];
#pragma unroll
    for (int i = 0; i < 8; i++) acc[i] = 0.f;
    const float4* wa = (const float4*)wsa + jt;
    const float4* wb = (const float4*)wsb + jt;
#pragma unroll 8
    for (int k = 0; k < 128; k++) {
        float xf = xsT[k * 33 + r];
        float4 a = wa[k * 8];
        float4 b = wb[k * 8];
        acc[0] = fmaf(xf, a.x, acc[0]); acc[1] = fmaf(xf, a.y, acc[1]);
        acc[2] = fmaf(xf, a.z, acc[2]); acc[3] = fmaf(xf, a.w, acc[3]);
        acc[4] = fmaf(xf, b.x, acc[4]); acc[5] = fmaf(xf, b.y, acc[5]);
        acc[6] = fmaf(xf, b.z, acc[6]); acc[7] = fmaf(xf, b.w, acc[7]);
    }
    int row = row0 + r;
    if (row < n) {
        float di = g_dis[row];                       // prescale by dis[row]
        float4* o = (float4*)(g_h0 + (size_t)row * 64 + jt * 8);
        o[0] = make_float4(di*acc[0], di*acc[1], di*acc[2], di*acc[3]);
        o[1] = make_float4(di*acc[4], di*acc[5], di*acc[6], di*acc[7]);
    }
}

// ---------------- GEMM 2: g_gg = dis[row] * (h[N,64] @ interleave(Wmu,Wls)) ----------------
__global__ void __launch_bounds__(256) gemm2_kernel(const float* __restrict__ Wmu,
                                                    const float* __restrict__ Wls, int n) {
    __shared__ float wsa[64 * 32];
    __shared__ float wsb[64 * 32];
    __shared__ float xsT[64 * 33];
    int tid = threadIdx.x;
    for (int i = tid; i < 64 * 64; i += 256) {
        int k = i >> 6, j = i & 63;
        float v = (j < 32) ? Wmu[k * 32 + j] : Wls[k * 32 + (j - 32)];
        int jn = (j < 32) ? (2 * j) : (2 * (j - 32) + 1);   // interleave mu/ls columns
        int jt = jn >> 3, c = jn & 7;
        if (c < 4) wsa[k * 32 + jt * 4 + c] = v;
        else       wsb[k * 32 + jt * 4 + (c - 4)] = v;
    }
    int row0 = blockIdx.x * 32;
    for (int i = tid; i < 2048; i += 256) {
        int r = i >> 6, k = i & 63;
        int row = row0 + r;
        xsT[k * 33 + r] = (row < n) ? g_h[(size_t)row * 64 + k] : 0.f;
    }
    __syncthreads();
    int lane = tid & 31, wrp = tid >> 5;
    int r  = wrp * 4 + (lane >> 3);
    int jt = lane & 7;
    float acc[8];
#pragma unroll
    for (int i = 0; i < 8; i++) acc[i] = 0.f;
    const float4* wa = (const float4*)wsa + jt;
    const float4* wb = (const float4*)wsb + jt;
#pragma unroll 8
    for (int k = 0; k < 64; k++) {
        float xf = xsT[k * 33 + r];
        float4 a = wa[k * 8];
        float4 b = wb[k * 8];
        acc[0] = fmaf(xf, a.x, acc[0]); acc[1] = fmaf(xf, a.y, acc[1]);
        acc[2] = fmaf(xf, a.z, acc[2]); acc[3] = fmaf(xf, a.w, acc[3]);
        acc[4] = fmaf(xf, b.x, acc[4]); acc[5] = fmaf(xf, b.y, acc[5]);
        acc[6] = fmaf(xf, b.z, acc[6]); acc[7] = fmaf(xf, b.w, acc[7]);
    }
    int row = row0 + r;
    if (row < n) {
        float di = g_dis[row];
        float4* o = (float4*)(g_gg + (size_t)row * 64 + jt * 8);
        o[0] = make_float4(di*acc[0], di*acc[1], di*acc[2], di*acc[3]);
        o[1] = make_float4(di*acc[4], di*acc[5], di*acc[6], di*acc[7]);
    }
}

// ---------------- Conv1: warp/node, unroll-8 gather ----------------
__global__ void __launch_bounds__(256) conv1_kernel(const float* __restrict__ b1, int n) {
    int node = blockIdx.x * 8 + (threadIdx.x >> 5);
    int t    = threadIdx.x & 31;
    if (node >= n) return;
    int st  = g_rowstart[node];
    int cnt = g_indeg[node];
    const int* cs = g_csr + st;
    const float* hb = g_h0 + 2 * t;
    float a0x = 0.f, a0y = 0.f, a1x = 0.f, a1y = 0.f;
    int e = 0;
    for (; e + 8 <= cnt; e += 8) {
        int s0 = cs[e], s1 = cs[e+1], s2 = cs[e+2], s3 = cs[e+3];
        int s4 = cs[e+4], s5 = cs[e+5], s6 = cs[e+6], s7 = cs[e+7];
        float2 v0 = *(const float2*)(hb + (size_t)s0 * 64);
        float2 v1 = *(const float2*)(hb + (size_t)s1 * 64);
        float2 v2 = *(const float2*)(hb + (size_t)s2 * 64);
        float2 v3 = *(const float2*)(hb + (size_t)s3 * 64);
        float2 v4 = *(const float2*)(hb + (size_t)s4 * 64);
        float2 v5 = *(const float2*)(hb + (size_t)s5 * 64);
        float2 v6 = *(const float2*)(hb + (size_t)s6 * 64);
        float2 v7 = *(const float2*)(hb + (size_t)s7 * 64);
        a0x += v0.x; a0y += v0.y; a1x += v1.x; a1y += v1.y;
        a0x += v2.x; a0y += v2.y; a1x += v3.x; a1y += v3.y;
        a0x += v4.x; a0y += v4.y; a1x += v5.x; a1y += v5.y;
        a0x += v6.x; a0y += v6.y; a1x += v7.x; a1y += v7.y;
    }
    for (; e < cnt; e++) {
        float2 v = *(const float2*)(hb + (size_t)cs[e] * 64);
        a0x += v.x; a0y += v.y;
    }
    float2 self = *(const float2*)(hb + (size_t)node * 64);
    float sx = a0x + a1x + self.x;
    float sy = a0y + a1y + self.y;
    float di = g_dis[node];
    float2 bb = *(const float2*)(b1 + 2 * t);
    float vx = fmaxf(fmaf(di, sx, bb.x), 0.f);
    float vy = fmaxf(fmaf(di, sy, bb.y), 0.f);
    float ss = vx * vx + vy * vy;
#pragma unroll
    for (int o = 16; o > 0; o >>= 1) ss += __shfl_xor_sync(0xffffffffu, ss, o);
    float scale = 1.0f / fmaxf(sqrtf(ss), 1e-12f);
    *(float2*)(g_h + (size_t)node * 64 + 2 * t) = make_float2(vx * scale, vy * scale);
}

// ---------------- Conv2 + reparametrize ----------------
__global__ void __launch_bounds__(256) conv2_kernel(const float* __restrict__ bmu,
                                                    const float* __restrict__ bls,
                                                    const float* __restrict__ eps,
                                                    float* __restrict__ out_mu,
                                                    float* __restrict__ out_ls, int n) {
    int node = blockIdx.x * 8 + (threadIdx.x >> 5);
    int t    = threadIdx.x & 31;
    if (node >= n) return;
    int st  = g_rowstart[node];
    int cnt = g_indeg[node];
    const int* cs = g_csr + st;
    const float* gb = g_gg + 2 * t;
    float a0x = 0.f, a0y = 0.f, a1x = 0.f, a1y = 0.f;
    int e = 0;
    for (; e + 8 <= cnt; e += 8) {
        int s0 = cs[e], s1 = cs[e+1], s2 = cs[e+2], s3 = cs[e+3];
        int s4 = cs[e+4], s5 = cs[e+5], s6 = cs[e+6], s7 = cs[e+7];
        float2 v0 = *(const float2*)(gb + (size_t)s0 * 64);
        float2 v1 = *(const float2*)(gb + (size_t)s1 * 64);
        float2 v2 = *(const float2*)(gb + (size_t)s2 * 64);
        float2 v3 = *(const float2*)(gb + (size_t)s3 * 64);
        float2 v4 = *(const float2*)(gb + (size_t)s4 * 64);
        float2 v5 = *(const float2*)(gb + (size_t)s5 * 64);
        float2 v6 = *(const float2*)(gb + (size_t)s6 * 64);
        float2 v7 = *(const float2*)(gb + (size_t)s7 * 64);
        a0x += v0.x; a0y += v0.y; a1x += v1.x; a1y += v1.y;
        a0x += v2.x; a0y += v2.y; a1x += v3.x; a1y += v3.y;
        a0x += v4.x; a0y += v4.y; a1x += v5.x; a1y += v5.y;
        a0x += v6.x; a0y += v6.y; a1x += v7.x; a1y += v7.y;
    }
    for (; e < cnt; e++) {
        float2 v = *(const float2*)(gb + (size_t)cs[e] * 64);
        a0x += v.x; a0y += v.y;
    }
    float2 self = *(const float2*)(gb + (size_t)node * 64);
    float sx = a0x + a1x + self.x;
    float sy = a0y + a1y + self.y;
    float di = g_dis[node];
    float mu = fmaf(di, sx, bmu[t]);
    float ls = fmaf(di, sy, bls[t]);
    size_t oi = (size_t)node * 32 + t;
    out_mu[oi] = mu;
    out_ls[oi] = ls;
    float lc = fminf(fmaxf(ls, -10.f), 10.f);
    g_z[oi] = fmaf(eps[oi], __expf(lc), mu);
}

// ---------------- decode: 8 lanes/edge ----------------
__global__ void __launch_bounds__(256) decode_kernel(const int* __restrict__ src,
                                                     const int* __restrict__ dst,
                                                     float* __restrict__ out, int E) {
    int gid = blockIdx.x * 256 + threadIdx.x;
    int e   = gid >> 3;
    int sub = gid & 7;
    if (e >= E) return;
    int s = src[e], d = dst[e];
    float4 a = *(const float4*)(g_z + (size_t)s * 32 + sub * 4);
    float4 b = *(const float4*)(g_z + (size_t)d * 32 + sub * 4);
    float p = a.x * b.x + a.y * b.y + a.z * b.z + a.w * b.w;
    p += __shfl_xor_sync(0xffffffffu, p, 1);
    p += __shfl_xor_sync(0xffffffffu, p, 2);
    p += __shfl_xor_sync(0xffffffffu, p, 4);
    if (sub == 0) out[e] = 1.0f / (1.0f + __expf(-p));
}

// ---------------- launch ----------------
extern "C" void kernel_launch(void* const* d_in, const int* in_sizes, int n_in,
                              void* d_out, int out_size) {
    const float* x   = (const float*)d_in[0];
    const int*   ei  = (const int*)  d_in[1];
    const float* eps = (const float*)d_in[2];
    const float* W1  = (const float*)d_in[3];
    const float* b1  = (const float*)d_in[4];
    const float* Wmu = (const float*)d_in[5];
    const float* bmu = (const float*)d_in[6];
    const float* Wls = (const float*)d_in[7];
    const float* bls = (const float*)d_in[8];

    int n = in_sizes[0] / 128;
    int E = in_sizes[1] / 2;
    const int* src = ei;
    const int* dst = ei + E;

    float* out     = (float*)d_out;
    float* out_adj = out;
    float* out_mu  = out + E;
    float* out_ls  = out + E + (size_t)n * 32;

    // host-side resources for graph fork/join (created per call; no device mem)
    cudaStream_t s2;
    cudaEvent_t evFork, evJoin;
    cudaStreamCreateWithFlags(&s2, cudaStreamNonBlocking);
    cudaEventCreateWithFlags(&evFork, cudaEventDisableTiming);
    cudaEventCreateWithFlags(&evJoin, cudaEventDisableTiming);

    init_kernel<<<(n + 255) / 256, 256>>>(n);
    hist_kernel<<<(E + 255) / 256, 256>>>(dst, E);
    dis_kernel<<<(n + 255) / 256, 256>>>(n);

    // fork: gemm1 depends only on {x, W1, dis}; CSR build runs concurrently
    cudaEventRecord(evFork, 0);
    cudaStreamWaitEvent(s2, evFork, 0);
    gemm1_kernel<<<(n + 31) / 32, 256, 0, s2>>>(x, W1, n);
    cudaEventRecord(evJoin, s2);

    int nb = (n + 1023) / 1024;
    scan1_kernel<<<nb, 1024>>>(n);
    scan2_kernel<<<1, 256>>>(nb);
    scan3_kernel<<<(n + 255) / 256, 256>>>(n);
    fill_kernel<<<(E + 255) / 256, 256>>>(src, dst, E);

    // join: conv1 needs both CSR and g_h0
    cudaStreamWaitEvent(0, evJoin, 0);

    conv1_kernel<<<(n + 7) / 8, 256>>>(b1, n);
    gemm2_kernel<<<(n + 31) / 32, 256>>>(Wmu, Wls, n);
    conv2_kernel<<<(n + 7) / 8, 256>>>(bmu, bls, eps, out_mu, out_ls, n);
    decode_kernel<<<((size_t)E * 8 + 255) / 256, 256>>>(src, dst, out_adj, E);
}

// round 6
// speedup vs baseline: 2.0595x; 1.5670x over previous
#include <cuda_runtime.h>
#include <math.h>

#define MAXN 100000
#define MAXE 1600000

// ---------------- scratch ----------------
__device__ int   g_indeg[MAXN];
__device__ int   g_rowstart[MAXN];
__device__ int   g_cursor[MAXN];
__device__ int   g_bsum[256];
__device__ float g_dis[MAXN];
__device__ int   g_csr[MAXE];              // src only (weights folded into row prescale)
__device__ float g_h0[(size_t)MAXN * 64];  // dis[row]-prescaled x@W1
__device__ float g_h [(size_t)MAXN * 64];  // normalized hidden
__device__ float g_gg[(size_t)MAXN * 64];  // dis-prescaled, (mu_j,ls_j) interleaved
__device__ float g_z [(size_t)MAXN * 32];

// ---------------- graph preprocessing ----------------
__global__ void init_kernel(int n) {
    int i = blockIdx.x * blockDim.x + threadIdx.x;
    if (i < n) g_indeg[i] = 0;
}

__global__ void hist_kernel(const int* __restrict__ dst, int E) {
    int e = blockIdx.x * blockDim.x + threadIdx.x;
    if (e < E) atomicAdd(&g_indeg[dst[e]], 1);
}

__global__ void dis_kernel(int n) {
    int i = blockIdx.x * blockDim.x + threadIdx.x;
    if (i < n) g_dis[i] = rsqrtf((float)(g_indeg[i] + 1));
}

__global__ void scan1_kernel(int n) {
    __shared__ int sm[1024];
    int t = threadIdx.x;
    int i = blockIdx.x * 1024 + t;
    int v = (i < n) ? g_indeg[i] : 0;
    sm[t] = v;
    __syncthreads();
#pragma unroll
    for (int o = 1; o < 1024; o <<= 1) {
        int tv = (t >= o) ? sm[t - o] : 0;
        __syncthreads();
        sm[t] += tv;
        __syncthreads();
    }
    if (i < n) g_rowstart[i] = sm[t] - v;
    if (t == 1023) g_bsum[blockIdx.x] = sm[1023];
}

__global__ void scan2_kernel(int nb) {
    __shared__ int sm[256];
    int t = threadIdx.x;
    int v = (t < nb) ? g_bsum[t] : 0;
    sm[t] = v;
    __syncthreads();
#pragma unroll
    for (int o = 1; o < 256; o <<= 1) {
        int tv = (t >= o) ? sm[t - o] : 0;
        __syncthreads();
        sm[t] += tv;
        __syncthreads();
    }
    if (t < nb) g_bsum[t] = sm[t] - v;
}

__global__ void scan3_kernel(int n) {
    int i = blockIdx.x * blockDim.x + threadIdx.x;
    if (i < n) {
        int v = g_rowstart[i] + g_bsum[i >> 10];
        g_rowstart[i] = v;
        g_cursor[i]   = v;
    }
}

__global__ void fill_kernel(const int* __restrict__ src, const int* __restrict__ dst, int E) {
    int e = blockIdx.x * blockDim.x + threadIdx.x;
    if (e < E) {
        int p = atomicAdd(&g_cursor[dst[e]], 1);
        g_csr[p] = src[e];
    }
}

// ============ GEMM 1: g_h0 = dis[row] * (x[N,128] @ W1[128,64]) =============
// 128 rows x 64 cols per block; thread = 4 rows x 8 cols; k-chunks of 32.
// dyn smem: wsa[128*32] wsb[128*32] xs[32*132] = 49664 B
__global__ void __launch_bounds__(256) gemm1_kernel(const float* __restrict__ x,
                                                    const float* __restrict__ W, int n) {
    extern __shared__ float sm[];
    float* wsa = sm;            // cols jt*8..+3  at [k*32 + jt*4]
    float* wsb = sm + 4096;     // cols jt*8+4..+7
    float* xs  = sm + 8192;     // [kk][row^swz], stride 132
    int tid = threadIdx.x;
    for (int i = tid; i < 128 * 64; i += 256) {
        int k = i >> 6, j = i & 63;
        float v = W[i];
        int jt = j >> 3, c = j & 7;
        if (c < 4) wsa[k * 32 + jt * 4 + c] = v;
        else       wsb[k * 32 + jt * 4 + (c - 4)] = v;
    }
    int row0 = blockIdx.x * 128;
    int lane = tid & 31, wrp = tid >> 5;
    int rg4 = (wrp * 4 + (lane >> 3)) * 4;   // thread's first row (of 4)
    int jt  = lane & 7;
    float acc[4][8];
#pragma unroll
    for (int i = 0; i < 4; i++)
#pragma unroll
        for (int j = 0; j < 8; j++) acc[i][j] = 0.f;

    int frow = tid >> 3;                     // fill: row base 0..31
    int kq   = tid & 7;                      // fill: k-quad 0..7
    int csw  = ((kq & 3) << 3) | ((kq >> 2) << 2);   // swizzle

    for (int kc = 0; kc < 4; kc++) {
        __syncthreads();
#pragma unroll
        for (int it = 0; it < 4; it++) {
            int row  = frow + it * 32;
            int grow = row0 + row;
            float4 v = (grow < n) ? *(const float4*)(x + (size_t)grow * 128 + kc * 32 + kq * 4)
                                  : make_float4(0.f, 0.f, 0.f, 0.f);
            int rs = row ^ csw;
            xs[(kq * 4 + 0) * 132 + rs] = v.x;
            xs[(kq * 4 + 1) * 132 + rs] = v.y;
            xs[(kq * 4 + 2) * 132 + rs] = v.z;
            xs[(kq * 4 + 3) * 132 + rs] = v.w;
        }
        __syncthreads();
#pragma unroll
        for (int kk = 0; kk < 32; kk++) {
            int c = (((kk >> 2) & 3) << 3) | (((kk >> 4) & 1) << 2);
            float4 xv = *(const float4*)(xs + kk * 132 + (rg4 ^ c));
            int k = kc * 32 + kk;
            float4 a = *(const float4*)(wsa + k * 32 + jt * 4);
            float4 b = *(const float4*)(wsb + k * 32 + jt * 4);
            float xr[4] = {xv.x, xv.y, xv.z, xv.w};
#pragma unroll
            for (int i = 0; i < 4; i++) {
                acc[i][0] = fmaf(xr[i], a.x, acc[i][0]);
                acc[i][1] = fmaf(xr[i], a.y, acc[i][1]);
                acc[i][2] = fmaf(xr[i], a.z, acc[i][2]);
                acc[i][3] = fmaf(xr[i], a.w, acc[i][3]);
                acc[i][4] = fmaf(xr[i], b.x, acc[i][4]);
                acc[i][5] = fmaf(xr[i], b.y, acc[i][5]);
                acc[i][6] = fmaf(xr[i], b.z, acc[i][6]);
                acc[i][7] = fmaf(xr[i], b.w, acc[i][7]);
            }
        }
    }
#pragma unroll
    for (int i = 0; i < 4; i++) {
        int rr = row0 + rg4 + i;
        if (rr < n) {
            float di = g_dis[rr];
            float4* o = (float4*)(g_h0 + (size_t)rr * 64 + jt * 8);
            o[0] = make_float4(di*acc[i][0], di*acc[i][1], di*acc[i][2], di*acc[i][3]);
            o[1] = make_float4(di*acc[i][4], di*acc[i][5], di*acc[i][6], di*acc[i][7]);
        }
    }
}

// ====== GEMM 2: g_gg = dis[row] * (h[N,64] @ interleave(Wmu,Wls)) ======
// dyn smem: wsa[64*32] wsb[64*32] xs[32*132] = 33280 B
__global__ void __launch_bounds__(256) gemm2_kernel(const float* __restrict__ Wmu,
                                                    const float* __restrict__ Wls, int n) {
    extern __shared__ float sm[];
    float* wsa = sm;
    float* wsb = sm + 2048;
    float* xs  = sm + 4096;
    int tid = threadIdx.x;
    for (int i = tid; i < 64 * 64; i += 256) {
        int k = i >> 6, j = i & 63;
        float v = (j < 32) ? Wmu[k * 32 + j] : Wls[k * 32 + (j - 32)];
        int jn = (j < 32) ? (2 * j) : (2 * (j - 32) + 1);   // interleave mu/ls
        int jt = jn >> 3, c = jn & 7;
        if (c < 4) wsa[k * 32 + jt * 4 + c] = v;
        else       wsb[k * 32 + jt * 4 + (c - 4)] = v;
    }
    int row0 = blockIdx.x * 128;
    int lane = tid & 31, wrp = tid >> 5;
    int rg4 = (wrp * 4 + (lane >> 3)) * 4;
    int jt  = lane & 7;
    float acc[4][8];
#pragma unroll
    for (int i = 0; i < 4; i++)
#pragma unroll
        for (int j = 0; j < 8; j++) acc[i][j] = 0.f;

    int frow = tid >> 3;
    int kq   = tid & 7;
    int csw  = ((kq & 3) << 3) | ((kq >> 2) << 2);

    for (int kc = 0; kc < 2; kc++) {
        __syncthreads();
#pragma unroll
        for (int it = 0; it < 4; it++) {
            int row  = frow + it * 32;
            int grow = row0 + row;
            float4 v = (grow < n) ? *(const float4*)(g_h + (size_t)grow * 64 + kc * 32 + kq * 4)
                                  : make_float4(0.f, 0.f, 0.f, 0.f);
            int rs = row ^ csw;
            xs[(kq * 4 + 0) * 132 + rs] = v.x;
            xs[(kq * 4 + 1) * 132 + rs] = v.y;
            xs[(kq * 4 + 2) * 132 + rs] = v.z;
            xs[(kq * 4 + 3) * 132 + rs] = v.w;
        }
        __syncthreads();
#pragma unroll
        for (int kk = 0; kk < 32; kk++) {
            int c = (((kk >> 2) & 3) << 3) | (((kk >> 4) & 1) << 2);
            float4 xv = *(const float4*)(xs + kk * 132 + (rg4 ^ c));
            int k = kc * 32 + kk;
            float4 a = *(const float4*)(wsa + k * 32 + jt * 4);
            float4 b = *(const float4*)(wsb + k * 32 + jt * 4);
            float xr[4] = {xv.x, xv.y, xv.z, xv.w};
#pragma unroll
            for (int i = 0; i < 4; i++) {
                acc[i][0] = fmaf(xr[i], a.x, acc[i][0]);
                acc[i][1] = fmaf(xr[i], a.y, acc[i][1]);
                acc[i][2] = fmaf(xr[i], a.z, acc[i][2]);
                acc[i][3] = fmaf(xr[i], a.w, acc[i][3]);
                acc[i][4] = fmaf(xr[i], b.x, acc[i][4]);
                acc[i][5] = fmaf(xr[i], b.y, acc[i][5]);
                acc[i][6] = fmaf(xr[i], b.z, acc[i][6]);
                acc[i][7] = fmaf(xr[i], b.w, acc[i][7]);
            }
        }
    }
#pragma unroll
    for (int i = 0; i < 4; i++) {
        int rr = row0 + rg4 + i;
        if (rr < n) {
            float di = g_dis[rr];
            float4* o = (float4*)(g_gg + (size_t)rr * 64 + jt * 8);
            o[0] = make_float4(di*acc[i][0], di*acc[i][1], di*acc[i][2], di*acc[i][3]);
            o[1] = make_float4(di*acc[i][4], di*acc[i][5], di*acc[i][6], di*acc[i][7]);
        }
    }
}

// ---------------- Conv1: warp/node, unroll-8 gather ----------------
__global__ void __launch_bounds__(256) conv1_kernel(const float* __restrict__ b1, int n) {
    int node = blockIdx.x * 8 + (threadIdx.x >> 5);
    int t    = threadIdx.x & 31;
    if (node >= n) return;
    int st  = g_rowstart[node];
    int cnt = g_indeg[node];
    const int* cs = g_csr + st;
    const float* hb = g_h0 + 2 * t;
    float a0x = 0.f, a0y = 0.f, a1x = 0.f, a1y = 0.f;
    int e = 0;
    for (; e + 8 <= cnt; e += 8) {
        int s0 = cs[e], s1 = cs[e+1], s2 = cs[e+2], s3 = cs[e+3];
        int s4 = cs[e+4], s5 = cs[e+5], s6 = cs[e+6], s7 = cs[e+7];
        float2 v0 = *(const float2*)(hb + (size_t)s0 * 64);
        float2 v1 = *(const float2*)(hb + (size_t)s1 * 64);
        float2 v2 = *(const float2*)(hb + (size_t)s2 * 64);
        float2 v3 = *(const float2*)(hb + (size_t)s3 * 64);
        float2 v4 = *(const float2*)(hb + (size_t)s4 * 64);
        float2 v5 = *(const float2*)(hb + (size_t)s5 * 64);
        float2 v6 = *(const float2*)(hb + (size_t)s6 * 64);
        float2 v7 = *(const float2*)(hb + (size_t)s7 * 64);
        a0x += v0.x; a0y += v0.y; a1x += v1.x; a1y += v1.y;
        a0x += v2.x; a0y += v2.y; a1x += v3.x; a1y += v3.y;
        a0x += v4.x; a0y += v4.y; a1x += v5.x; a1y += v5.y;
        a0x += v6.x; a0y += v6.y; a1x += v7.x; a1y += v7.y;
    }
    for (; e < cnt; e++) {
        float2 v = *(const float2*)(hb + (size_t)cs[e] * 64);
        a0x += v.x; a0y += v.y;
    }
    float2 self = *(const float2*)(hb + (size_t)node * 64);
    float sx = a0x + a1x + self.x;
    float sy = a0y + a1y + self.y;
    float di = g_dis[node];
    float2 bb = *(const float2*)(b1 + 2 * t);
    float vx = fmaxf(fmaf(di, sx, bb.x), 0.f);
    float vy = fmaxf(fmaf(di, sy, bb.y), 0.f);
    float ss = vx * vx + vy * vy;
#pragma unroll
    for (int o = 16; o > 0; o >>= 1) ss += __shfl_xor_sync(0xffffffffu, ss, o);
    float scale = 1.0f / fmaxf(sqrtf(ss), 1e-12f);
    *(float2*)(g_h + (size_t)node * 64 + 2 * t) = make_float2(vx * scale, vy * scale);
}

// ---------------- Conv2 + reparametrize ----------------
__global__ void __launch_bounds__(256) conv2_kernel(const float* __restrict__ bmu,
                                                    const float* __restrict__ bls,
                                                    const float* __restrict__ eps,
                                                    float* __restrict__ out_mu,
                                                    float* __restrict__ out_ls, int n) {
    int node = blockIdx.x * 8 + (threadIdx.x >> 5);
    int t    = threadIdx.x & 31;
    if (node >= n) return;
    int st  = g_rowstart[node];
    int cnt = g_indeg[node];
    const int* cs = g_csr + st;
    const float* gb = g_gg + 2 * t;
    float a0x = 0.f, a0y = 0.f, a1x = 0.f, a1y = 0.f;
    int e = 0;
    for (; e + 8 <= cnt; e += 8) {
        int s0 = cs[e], s1 = cs[e+1], s2 = cs[e+2], s3 = cs[e+3];
        int s4 = cs[e+4], s5 = cs[e+5], s6 = cs[e+6], s7 = cs[e+7];
        float2 v0 = *(const float2*)(gb + (size_t)s0 * 64);
        float2 v1 = *(const float2*)(gb + (size_t)s1 * 64);
        float2 v2 = *(const float2*)(gb + (size_t)s2 * 64);
        float2 v3 = *(const float2*)(gb + (size_t)s3 * 64);
        float2 v4 = *(const float2*)(gb + (size_t)s4 * 64);
        float2 v5 = *(const float2*)(gb + (size_t)s5 * 64);
        float2 v6 = *(const float2*)(gb + (size_t)s6 * 64);
        float2 v7 = *(const float2*)(gb + (size_t)s7 * 64);
        a0x += v0.x; a0y += v0.y; a1x += v1.x; a1y += v1.y;
        a0x += v2.x; a0y += v2.y; a1x += v3.x; a1y += v3.y;
        a0x += v4.x; a0y += v4.y; a1x += v5.x; a1y += v5.y;
        a0x += v6.x; a0y += v6.y; a1x += v7.x; a1y += v7.y;
    }
    for (; e < cnt; e++) {
        float2 v = *(const float2*)(gb + (size_t)cs[e] * 64);
        a0x += v.x; a0y += v.y;
    }
    float2 self = *(const float2*)(gb + (size_t)node * 64);
    float sx = a0x + a1x + self.x;
    float sy = a0y + a1y + self.y;
    float di = g_dis[node];
    float mu = fmaf(di, sx, bmu[t]);
    float ls = fmaf(di, sy, bls[t]);
    size_t oi = (size_t)node * 32 + t;
    out_mu[oi] = mu;
    out_ls[oi] = ls;
    float lc = fminf(fmaxf(ls, -10.f), 10.f);
    g_z[oi] = fmaf(eps[oi], __expf(lc), mu);
}

// ---------------- decode: 8 lanes/edge ----------------
__global__ void __launch_bounds__(256) decode_kernel(const int* __restrict__ src,
                                                     const int* __restrict__ dst,
                                                     float* __restrict__ out, int E) {
    int gid = blockIdx.x * 256 + threadIdx.x;
    int e   = gid >> 3;
    int sub = gid & 7;
    if (e >= E) return;
    int s = src[e], d = dst[e];
    float4 a = *(const float4*)(g_z + (size_t)s * 32 + sub * 4);
    float4 b = *(const float4*)(g_z + (size_t)d * 32 + sub * 4);
    float p = a.x * b.x + a.y * b.y + a.z * b.z + a.w * b.w;
    p += __shfl_xor_sync(0xffffffffu, p, 1);
    p += __shfl_xor_sync(0xffffffffu, p, 2);
    p += __shfl_xor_sync(0xffffffffu, p, 4);
    if (sub == 0) out[e] = 1.0f / (1.0f + __expf(-p));
}

// ---------------- launch ----------------
extern "C" void kernel_launch(void* const* d_in, const int* in_sizes, int n_in,
                              void* d_out, int out_size) {
    const float* x   = (const float*)d_in[0];
    const int*   ei  = (const int*)  d_in[1];
    const float* eps = (const float*)d_in[2];
    const float* W1  = (const float*)d_in[3];
    const float* b1  = (const float*)d_in[4];
    const float* Wmu = (const float*)d_in[5];
    const float* bmu = (const float*)d_in[6];
    const float* Wls = (const float*)d_in[7];
    const float* bls = (const float*)d_in[8];

    int n = in_sizes[0] / 128;
    int E = in_sizes[1] / 2;
    const int* src = ei;
    const int* dst = ei + E;

    float* out     = (float*)d_out;
    float* out_adj = out;
    float* out_mu  = out + E;
    float* out_ls  = out + E + (size_t)n * 32;

    const int SMEM1 = (4096 + 4096 + 32 * 132) * 4;   // 49664
    const int SMEM2 = (2048 + 2048 + 32 * 132) * 4;   // 33280
    cudaFuncSetAttribute(gemm1_kernel, cudaFuncAttributeMaxDynamicSharedMemorySize, SMEM1);
    cudaFuncSetAttribute(gemm2_kernel, cudaFuncAttributeMaxDynamicSharedMemorySize, SMEM2);

    // host-side resources for graph fork/join (no device mem)
    cudaStream_t s2;
    cudaEvent_t evFork, evJoin;
    cudaStreamCreateWithFlags(&s2, cudaStreamNonBlocking);
    cudaEventCreateWithFlags(&evFork, cudaEventDisableTiming);
    cudaEventCreateWithFlags(&evJoin, cudaEventDisableTiming);

    init_kernel<<<(n + 255) / 256, 256>>>(n);
    hist_kernel<<<(E + 255) / 256, 256>>>(dst, E);
    dis_kernel<<<(n + 255) / 256, 256>>>(n);

    // fork: gemm1 depends only on {x, W1, dis}
    cudaEventRecord(evFork, 0);
    cudaStreamWaitEvent(s2, evFork, 0);
    gemm1_kernel<<<(n + 127) / 128, 256, SMEM1, s2>>>(x, W1, n);
    cudaEventRecord(evJoin, s2);

    int nb = (n + 1023) / 1024;
    scan1_kernel<<<nb, 1024>>>(n);
    scan2_kernel<<<1, 256>>>(nb);
    scan3_kernel<<<(n + 255) / 256, 256>>>(n);
    fill_kernel<<<(E + 255) / 256, 256>>>(src, dst, E);

    cudaStreamWaitEvent(0, evJoin, 0);

    conv1_kernel<<<(n + 7) / 8, 256>>>(b1, n);
    gemm2_kernel<<<(n + 127) / 128, 256, SMEM2>>>(Wmu, Wls, n);
    conv2_kernel<<<(n + 7) / 8, 256>>>(bmu, bls, eps, out_mu, out_ls, n);
    decode_kernel<<<((size_t)E * 8 + 255) / 256, 256>>>(src, dst, out_adj, E);
}

// round 7
// speedup vs baseline: 2.1198x; 1.0293x over previous
#include <cuda_runtime.h>
#include <cuda_fp16.h>
#include <math.h>

#define MAXN 100000
#define MAXE 1600000

// ---------------- scratch ----------------
__device__ int     g_indeg[MAXN];
__device__ int     g_rowstart[MAXN];
__device__ int     g_cursor[MAXN];
__device__ int     g_bsum[256];
__device__ float   g_dis[MAXN];
__device__ int     g_csr[MAXE];                 // src only (weights folded into prescale)
__device__ __half2 g_h0h[(size_t)MAXN * 32];    // fp16: dis[row]-prescaled x@W1 (64 halves/row)
__device__ float   g_h [(size_t)MAXN * 64];     // fp32: normalized hidden (gemm2 streams it)
__device__ __half2 g_ggh[(size_t)MAXN * 32];    // fp16: dis-prescaled, (mu_j,ls_j) half2 pairs
__device__ __half  g_zh [(size_t)MAXN * 32];    // fp16: z

// ---------------- graph preprocessing ----------------
__global__ void init_kernel(int n) {
    int i = blockIdx.x * blockDim.x + threadIdx.x;
    if (i < n) g_indeg[i] = 0;
}

__global__ void hist_kernel(const int* __restrict__ dst, int E) {
    int e = blockIdx.x * blockDim.x + threadIdx.x;
    if (e < E) atomicAdd(&g_indeg[dst[e]], 1);
}

__global__ void dis_kernel(int n) {
    int i = blockIdx.x * blockDim.x + threadIdx.x;
    if (i < n) g_dis[i] = rsqrtf((float)(g_indeg[i] + 1));
}

__global__ void scan1_kernel(int n) {
    __shared__ int sm[1024];
    int t = threadIdx.x;
    int i = blockIdx.x * 1024 + t;
    int v = (i < n) ? g_indeg[i] : 0;
    sm[t] = v;
    __syncthreads();
#pragma unroll
    for (int o = 1; o < 1024; o <<= 1) {
        int tv = (t >= o) ? sm[t - o] : 0;
        __syncthreads();
        sm[t] += tv;
        __syncthreads();
    }
    if (i < n) g_rowstart[i] = sm[t] - v;
    if (t == 1023) g_bsum[blockIdx.x] = sm[1023];
}

__global__ void scan2_kernel(int nb) {
    __shared__ int sm[256];
    int t = threadIdx.x;
    int v = (t < nb) ? g_bsum[t] : 0;
    sm[t] = v;
    __syncthreads();
#pragma unroll
    for (int o = 1; o < 256; o <<= 1) {
        int tv = (t >= o) ? sm[t - o] : 0;
        __syncthreads();
        sm[t] += tv;
        __syncthreads();
    }
    if (t < nb) g_bsum[t] = sm[t] - v;
}

__global__ void scan3_kernel(int n) {
    int i = blockIdx.x * blockDim.x + threadIdx.x;
    if (i < n) {
        int v = g_rowstart[i] + g_bsum[i >> 10];
        g_rowstart[i] = v;
        g_cursor[i]   = v;
    }
}

__global__ void fill_kernel(const int* __restrict__ src, const int* __restrict__ dst, int E) {
    int e = blockIdx.x * blockDim.x + threadIdx.x;
    if (e < E) {
        int p = atomicAdd(&g_cursor[dst[e]], 1);
        g_csr[p] = src[e];
    }
}

// ============ GEMM 1: g_h0h = fp16( dis[row] * (x[N,128] @ W1[128,64]) ) ============
__global__ void __launch_bounds__(256) gemm1_kernel(const float* __restrict__ x,
                                                    const float* __restrict__ W, int n) {
    extern __shared__ float sm[];
    float* wsa = sm;
    float* wsb = sm + 4096;
    float* xs  = sm + 8192;
    int tid = threadIdx.x;
    for (int i = tid; i < 128 * 64; i += 256) {
        int k = i >> 6, j = i & 63;
        float v = W[i];
        int jt = j >> 3, c = j & 7;
        if (c < 4) wsa[k * 32 + jt * 4 + c] = v;
        else       wsb[k * 32 + jt * 4 + (c - 4)] = v;
    }
    int row0 = blockIdx.x * 128;
    int lane = tid & 31, wrp = tid >> 5;
    int rg4 = (wrp * 4 + (lane >> 3)) * 4;
    int jt  = lane & 7;
    float acc[4][8];
#pragma unroll
    for (int i = 0; i < 4; i++)
#pragma unroll
        for (int j = 0; j < 8; j++) acc[i][j] = 0.f;

    int frow = tid >> 3;
    int kq   = tid & 7;
    int csw  = ((kq & 3) << 3) | ((kq >> 2) << 2);

    for (int kc = 0; kc < 4; kc++) {
        __syncthreads();
#pragma unroll
        for (int it = 0; it < 4; it++) {
            int row  = frow + it * 32;
            int grow = row0 + row;
            float4 v = (grow < n) ? *(const float4*)(x + (size_t)grow * 128 + kc * 32 + kq * 4)
                                  : make_float4(0.f, 0.f, 0.f, 0.f);
            int rs = row ^ csw;
            xs[(kq * 4 + 0) * 132 + rs] = v.x;
            xs[(kq * 4 + 1) * 132 + rs] = v.y;
            xs[(kq * 4 + 2) * 132 + rs] = v.z;
            xs[(kq * 4 + 3) * 132 + rs] = v.w;
        }
        __syncthreads();
#pragma unroll
        for (int kk = 0; kk < 32; kk++) {
            int c = (((kk >> 2) & 3) << 3) | (((kk >> 4) & 1) << 2);
            float4 xv = *(const float4*)(xs + kk * 132 + (rg4 ^ c));
            int k = kc * 32 + kk;
            float4 a = *(const float4*)(wsa + k * 32 + jt * 4);
            float4 b = *(const float4*)(wsb + k * 32 + jt * 4);
            float xr[4] = {xv.x, xv.y, xv.z, xv.w};
#pragma unroll
            for (int i = 0; i < 4; i++) {
                acc[i][0] = fmaf(xr[i], a.x, acc[i][0]);
                acc[i][1] = fmaf(xr[i], a.y, acc[i][1]);
                acc[i][2] = fmaf(xr[i], a.z, acc[i][2]);
                acc[i][3] = fmaf(xr[i], a.w, acc[i][3]);
                acc[i][4] = fmaf(xr[i], b.x, acc[i][4]);
                acc[i][5] = fmaf(xr[i], b.y, acc[i][5]);
                acc[i][6] = fmaf(xr[i], b.z, acc[i][6]);
                acc[i][7] = fmaf(xr[i], b.w, acc[i][7]);
            }
        }
    }
#pragma unroll
    for (int i = 0; i < 4; i++) {
        int rr = row0 + rg4 + i;
        if (rr < n) {
            float di = g_dis[rr];
            __half2* o = g_h0h + (size_t)rr * 32 + jt * 4;
            o[0] = __floats2half2_rn(di*acc[i][0], di*acc[i][1]);
            o[1] = __floats2half2_rn(di*acc[i][2], di*acc[i][3]);
            o[2] = __floats2half2_rn(di*acc[i][4], di*acc[i][5]);
            o[3] = __floats2half2_rn(di*acc[i][6], di*acc[i][7]);
        }
    }
}

// ====== GEMM 2: g_ggh = fp16( dis[row] * (h[N,64] @ interleave(Wmu,Wls)) ) ======
__global__ void __launch_bounds__(256) gemm2_kernel(const float* __restrict__ Wmu,
                                                    const float* __restrict__ Wls, int n) {
    extern __shared__ float sm[];
    float* wsa = sm;
    float* wsb = sm + 2048;
    float* xs  = sm + 4096;
    int tid = threadIdx.x;
    for (int i = tid; i < 64 * 64; i += 256) {
        int k = i >> 6, j = i & 63;
        float v = (j < 32) ? Wmu[k * 32 + j] : Wls[k * 32 + (j - 32)];
        int jn = (j < 32) ? (2 * j) : (2 * (j - 32) + 1);
        int jt = jn >> 3, c = jn & 7;
        if (c < 4) wsa[k * 32 + jt * 4 + c] = v;
        else       wsb[k * 32 + jt * 4 + (c - 4)] = v;
    }
    int row0 = blockIdx.x * 128;
    int lane = tid & 31, wrp = tid >> 5;
    int rg4 = (wrp * 4 + (lane >> 3)) * 4;
    int jt  = lane & 7;
    float acc[4][8];
#pragma unroll
    for (int i = 0; i < 4; i++)
#pragma unroll
        for (int j = 0; j < 8; j++) acc[i][j] = 0.f;

    int frow = tid >> 3;
    int kq   = tid & 7;
    int csw  = ((kq & 3) << 3) | ((kq >> 2) << 2);

    for (int kc = 0; kc < 2; kc++) {
        __syncthreads();
#pragma unroll
        for (int it = 0; it < 4; it++) {
            int row  = frow + it * 32;
            int grow = row0 + row;
            float4 v = (grow < n) ? *(const float4*)(g_h + (size_t)grow * 64 + kc * 32 + kq * 4)
                                  : make_float4(0.f, 0.f, 0.f, 0.f);
            int rs = row ^ csw;
            xs[(kq * 4 + 0) * 132 + rs] = v.x;
            xs[(kq * 4 + 1) * 132 + rs] = v.y;
            xs[(kq * 4 + 2) * 132 + rs] = v.z;
            xs[(kq * 4 + 3) * 132 + rs] = v.w;
        }
        __syncthreads();
#pragma unroll
        for (int kk = 0; kk < 32; kk++) {
            int c = (((kk >> 2) & 3) << 3) | (((kk >> 4) & 1) << 2);
            float4 xv = *(const float4*)(xs + kk * 132 + (rg4 ^ c));
            int k = kc * 32 + kk;
            float4 a = *(const float4*)(wsa + k * 32 + jt * 4);
            float4 b = *(const float4*)(wsb + k * 32 + jt * 4);
            float xr[4] = {xv.x, xv.y, xv.z, xv.w};
#pragma unroll
            for (int i = 0; i < 4; i++) {
                acc[i][0] = fmaf(xr[i], a.x, acc[i][0]);
                acc[i][1] = fmaf(xr[i], a.y, acc[i][1]);
                acc[i][2] = fmaf(xr[i], a.z, acc[i][2]);
                acc[i][3] = fmaf(xr[i], a.w, acc[i][3]);
                acc[i][4] = fmaf(xr[i], b.x, acc[i][4]);
                acc[i][5] = fmaf(xr[i], b.y, acc[i][5]);
                acc[i][6] = fmaf(xr[i], b.z, acc[i][6]);
                acc[i][7] = fmaf(xr[i], b.w, acc[i][7]);
            }
        }
    }
#pragma unroll
    for (int i = 0; i < 4; i++) {
        int rr = row0 + rg4 + i;
        if (rr < n) {
            float di = g_dis[rr];
            __half2* o = g_ggh + (size_t)rr * 32 + jt * 4;
            o[0] = __floats2half2_rn(di*acc[i][0], di*acc[i][1]);
            o[1] = __floats2half2_rn(di*acc[i][2], di*acc[i][3]);
            o[2] = __floats2half2_rn(di*acc[i][4], di*acc[i][5]);
            o[3] = __floats2half2_rn(di*acc[i][6], di*acc[i][7]);
        }
    }
}

// ---------------- Conv1: warp/node, fp16 gather, fp32 accumulate ----------------
__global__ void __launch_bounds__(256) conv1_kernel(const float* __restrict__ b1, int n) {
    int node = blockIdx.x * 8 + (threadIdx.x >> 5);
    int t    = threadIdx.x & 31;
    if (node >= n) return;
    int st  = g_rowstart[node];
    int cnt = g_indeg[node];
    const int* cs = g_csr + st;
    const __half2* hb = g_h0h + t;
    float a0x = 0.f, a0y = 0.f, a1x = 0.f, a1y = 0.f;
    int e = 0;
    for (; e + 8 <= cnt; e += 8) {
        int s0 = cs[e], s1 = cs[e+1], s2 = cs[e+2], s3 = cs[e+3];
        int s4 = cs[e+4], s5 = cs[e+5], s6 = cs[e+6], s7 = cs[e+7];
        float2 v0 = __half22float2(hb[(size_t)s0 * 32]);
        float2 v1 = __half22float2(hb[(size_t)s1 * 32]);
        float2 v2 = __half22float2(hb[(size_t)s2 * 32]);
        float2 v3 = __half22float2(hb[(size_t)s3 * 32]);
        float2 v4 = __half22float2(hb[(size_t)s4 * 32]);
        float2 v5 = __half22float2(hb[(size_t)s5 * 32]);
        float2 v6 = __half22float2(hb[(size_t)s6 * 32]);
        float2 v7 = __half22float2(hb[(size_t)s7 * 32]);
        a0x += v0.x; a0y += v0.y; a1x += v1.x; a1y += v1.y;
        a0x += v2.x; a0y += v2.y; a1x += v3.x; a1y += v3.y;
        a0x += v4.x; a0y += v4.y; a1x += v5.x; a1y += v5.y;
        a0x += v6.x; a0y += v6.y; a1x += v7.x; a1y += v7.y;
    }
    for (; e < cnt; e++) {
        float2 v = __half22float2(hb[(size_t)cs[e] * 32]);
        a0x += v.x; a0y += v.y;
    }
    float2 self = __half22float2(hb[(size_t)node * 32]);
    float sx = a0x + a1x + self.x;
    float sy = a0y + a1y + self.y;
    float di = g_dis[node];
    float2 bb = *(const float2*)(b1 + 2 * t);
    float vx = fmaxf(fmaf(di, sx, bb.x), 0.f);
    float vy = fmaxf(fmaf(di, sy, bb.y), 0.f);
    float ss = vx * vx + vy * vy;
#pragma unroll
    for (int o = 16; o > 0; o >>= 1) ss += __shfl_xor_sync(0xffffffffu, ss, o);
    float scale = 1.0f / fmaxf(sqrtf(ss), 1e-12f);
    *(float2*)(g_h + (size_t)node * 64 + 2 * t) = make_float2(vx * scale, vy * scale);
}

// ---------------- Conv2 + reparametrize: fp16 gather, fp32 math ----------------
__global__ void __launch_bounds__(256) conv2_kernel(const float* __restrict__ bmu,
                                                    const float* __restrict__ bls,
                                                    const float* __restrict__ eps,
                                                    float* __restrict__ out_mu,
                                                    float* __restrict__ out_ls, int n) {
    int node = blockIdx.x * 8 + (threadIdx.x >> 5);
    int t    = threadIdx.x & 31;
    if (node >= n) return;
    int st  = g_rowstart[node];
    int cnt = g_indeg[node];
    const int* cs = g_csr + st;
    const __half2* gb = g_ggh + t;     // half2 at lane t = (mu_t, ls_t) contributions
    float a0x = 0.f, a0y = 0.f, a1x = 0.f, a1y = 0.f;
    int e = 0;
    for (; e + 8 <= cnt; e += 8) {
        int s0 = cs[e], s1 = cs[e+1], s2 = cs[e+2], s3 = cs[e+3];
        int s4 = cs[e+4], s5 = cs[e+5], s6 = cs[e+6], s7 = cs[e+7];
        float2 v0 = __half22float2(gb[(size_t)s0 * 32]);
        float2 v1 = __half22float2(gb[(size_t)s1 * 32]);
        float2 v2 = __half22float2(gb[(size_t)s2 * 32]);
        float2 v3 = __half22float2(gb[(size_t)s3 * 32]);
        float2 v4 = __half22float2(gb[(size_t)s4 * 32]);
        float2 v5 = __half22float2(gb[(size_t)s5 * 32]);
        float2 v6 = __half22float2(gb[(size_t)s6 * 32]);
        float2 v7 = __half22float2(gb[(size_t)s7 * 32]);
        a0x += v0.x; a0y += v0.y; a1x += v1.x; a1y += v1.y;
        a0x += v2.x; a0y += v2.y; a1x += v3.x; a1y += v3.y;
        a0x += v4.x; a0y += v4.y; a1x += v5.x; a1y += v5.y;
        a0x += v6.x; a0y += v6.y; a1x += v7.x; a1y += v7.y;
    }
    for (; e < cnt; e++) {
        float2 v = __half22float2(gb[(size_t)cs[e] * 32]);
        a0x += v.x; a0y += v.y;
    }
    float2 self = __half22float2(gb[(size_t)node * 32]);
    float sx = a0x + a1x + self.x;
    float sy = a0y + a1y + self.y;
    float di = g_dis[node];
    float mu = fmaf(di, sx, bmu[t]);
    float ls = fmaf(di, sy, bls[t]);
    size_t oi = (size_t)node * 32 + t;
    out_mu[oi] = mu;
    out_ls[oi] = ls;
    float lc = fminf(fmaxf(ls, -10.f), 10.f);
    g_zh[oi] = __float2half_rn(fmaf(eps[oi], __expf(lc), mu));
}

// ---------------- decode: 8 lanes/edge, fp16 z rows (64B each) ----------------
__global__ void __launch_bounds__(256) decode_kernel(const int* __restrict__ src,
                                                     const int* __restrict__ dst,
                                                     float* __restrict__ out, int E) {
    int gid = blockIdx.x * 256 + threadIdx.x;
    int e   = gid >> 3;
    int sub = gid & 7;
    if (e >= E) return;
    int s = src[e], d = dst[e];
    uint2 ua = *(const uint2*)(g_zh + (size_t)s * 32 + sub * 4);
    uint2 ub = *(const uint2*)(g_zh + (size_t)d * 32 + sub * 4);
    float2 a0 = __half22float2(*reinterpret_cast<__half2*>(&ua.x));
    float2 a1 = __half22float2(*reinterpret_cast<__half2*>(&ua.y));
    float2 b0 = __half22float2(*reinterpret_cast<__half2*>(&ub.x));
    float2 b1 = __half22float2(*reinterpret_cast<__half2*>(&ub.y));
    float p = a0.x * b0.x + a0.y * b0.y + a1.x * b1.x + a1.y * b1.y;
    p += __shfl_xor_sync(0xffffffffu, p, 1);
    p += __shfl_xor_sync(0xffffffffu, p, 2);
    p += __shfl_xor_sync(0xffffffffu, p, 4);
    if (sub == 0) out[e] = 1.0f / (1.0f + __expf(-p));
}

// ---------------- launch ----------------
extern "C" void kernel_launch(void* const* d_in, const int* in_sizes, int n_in,
                              void* d_out, int out_size) {
    const float* x   = (const float*)d_in[0];
    const int*   ei  = (const int*)  d_in[1];
    const float* eps = (const float*)d_in[2];
    const float* W1  = (const float*)d_in[3];
    const float* b1  = (const float*)d_in[4];
    const float* Wmu = (const float*)d_in[5];
    const float* bmu = (const float*)d_in[6];
    const float* Wls = (const float*)d_in[7];
    const float* bls = (const float*)d_in[8];

    int n = in_sizes[0] / 128;
    int E = in_sizes[1] / 2;
    const int* src = ei;
    const int* dst = ei + E;

    float* out     = (float*)d_out;
    float* out_adj = out;
    float* out_mu  = out + E;
    float* out_ls  = out + E + (size_t)n * 32;

    const int SMEM1 = (4096 + 4096 + 32 * 132) * 4;   // 49664
    const int SMEM2 = (2048 + 2048 + 32 * 132) * 4;   // 33280
    cudaFuncSetAttribute(gemm1_kernel, cudaFuncAttributeMaxDynamicSharedMemorySize, SMEM1);
    cudaFuncSetAttribute(gemm2_kernel, cudaFuncAttributeMaxDynamicSharedMemorySize, SMEM2);

    cudaStream_t s2;
    cudaEvent_t evFork, evJoin;
    cudaStreamCreateWithFlags(&s2, cudaStreamNonBlocking);
    cudaEventCreateWithFlags(&evFork, cudaEventDisableTiming);
    cudaEventCreateWithFlags(&evJoin, cudaEventDisableTiming);

    init_kernel<<<(n + 255) / 256, 256>>>(n);
    hist_kernel<<<(E + 255) / 256, 256>>>(dst, E);
    dis_kernel<<<(n + 255) / 256, 256>>>(n);

    // fork: gemm1 depends only on {x, W1, dis}
    cudaEventRecord(evFork, 0);
    cudaStreamWaitEvent(s2, evFork, 0);
    gemm1_kernel<<<(n + 127) / 128, 256, SMEM1, s2>>>(x, W1, n);
    cudaEventRecord(evJoin, s2);

    int nb = (n + 1023) / 1024;
    scan1_kernel<<<nb, 1024>>>(n);
    scan2_kernel<<<1, 256>>>(nb);
    scan3_kernel<<<(n + 255) / 256, 256>>>(n);
    fill_kernel<<<(E + 255) / 256, 256>>>(src, dst, E);

    cudaStreamWaitEvent(0, evJoin, 0);

    conv1_kernel<<<(n + 7) / 8, 256>>>(b1, n);
    gemm2_kernel<<<(n + 127) / 128, 256, SMEM2>>>(Wmu, Wls, n);
    conv2_kernel<<<(n + 7) / 8, 256>>>(bmu, bls, eps, out_mu, out_ls, n);
    decode_kernel<<<((size_t)E * 8 + 255) / 256, 256>>>(src, dst, out_adj, E);
}

// round 9
// speedup vs baseline: 2.2203x; 1.0474x over previous
#include <cuda_runtime.h>
#include <cuda_fp16.h>
#include <math.h>

#define MAXN 100000
#define MAXE 1600000

// ---------------- scratch ----------------
__device__ int     g_indeg[MAXN];
__device__ int     g_rowstart[MAXN];
__device__ int     g_cursor[MAXN];
__device__ int     g_bsum[256];
__device__ float   g_dis[MAXN];
__device__ int     g_csr[MAXE];
__device__ __half2 g_h0h[(size_t)MAXN * 32];    // fp16 dis-prescaled x@W1
__device__ float   g_h [(size_t)MAXN * 64];     // fp32 normalized hidden
__device__ __half2 g_ggh[(size_t)MAXN * 32];    // fp16 dis-prescaled (mu,ls) interleaved
__device__ __half  g_zh [(size_t)MAXN * 32];    // fp16 z

// ---------------- graph preprocessing ----------------
__global__ void init_kernel(int n) {
    int i = blockIdx.x * blockDim.x + threadIdx.x;
    if (i < n) g_indeg[i] = 0;
}

__global__ void hist_kernel(const int* __restrict__ dst, int E) {
    int e = blockIdx.x * blockDim.x + threadIdx.x;
    if (e < E) atomicAdd(&g_indeg[dst[e]], 1);
}

__global__ void dis_kernel(int n) {
    int i = blockIdx.x * blockDim.x + threadIdx.x;
    if (i < n) g_dis[i] = rsqrtf((float)(g_indeg[i] + 1));
}

__global__ void scan1_kernel(int n) {
    __shared__ int sm[1024];
    int t = threadIdx.x;
    int i = blockIdx.x * 1024 + t;
    int v = (i < n) ? g_indeg[i] : 0;
    sm[t] = v;
    __syncthreads();
#pragma unroll
    for (int o = 1; o < 1024; o <<= 1) {
        int tv = (t >= o) ? sm[t - o] : 0;
        __syncthreads();
        sm[t] += tv;
        __syncthreads();
    }
    if (i < n) g_rowstart[i] = sm[t] - v;
    if (t == 1023) g_bsum[blockIdx.x] = sm[1023];
}

__global__ void scan2_kernel(int nb) {
    __shared__ int sm[256];
    int t = threadIdx.x;
    int v = (t < nb) ? g_bsum[t] : 0;
    sm[t] = v;
    __syncthreads();
#pragma unroll
    for (int o = 1; o < 256; o <<= 1) {
        int tv = (t >= o) ? sm[t - o] : 0;
        __syncthreads();
        sm[t] += tv;
        __syncthreads();
    }
    if (t < nb) g_bsum[t] = sm[t] - v;
}

__global__ void scan3_kernel(int n) {
    int i = blockIdx.x * blockDim.x + threadIdx.x;
    if (i < n) {
        int v = g_rowstart[i] + g_bsum[i >> 10];
        g_rowstart[i] = v;
        g_cursor[i]   = v;
    }
}

__global__ void fill_kernel(const int* __restrict__ src, const int* __restrict__ dst, int E) {
    int e = blockIdx.x * blockDim.x + threadIdx.x;
    if (e < E) {
        int p = atomicAdd(&g_cursor[dst[e]], 1);
        g_csr[p] = src[e];
    }
}

// ============ GEMM 1: g_h0h = fp16( dis[row] * (x[N,128] @ W1[128,64]) ) ============
// block = 256 rows x 64 cols; thread = 8 rows x 8 cols; k-chunks of 32.
// xs: [kk][row] stride 256 with XOR swizzle (row ^ ((kk>>2)<<2)) — fills and
// LDS.128 reads both conflict-free, 16B-aligned.
__global__ void __launch_bounds__(256) gemm1_kernel(const float* __restrict__ x,
                                                    const float* __restrict__ W, int n) {
    extern __shared__ float sm[];
    float* wsa = sm;                 // [k][jt*4..+3] cols jt*8..+3
    float* wsb = sm + 4096;          // cols jt*8+4..+7
    float* xs  = sm + 8192;          // [kk][row^swz], stride 256
    int tid = threadIdx.x;
    for (int i = tid; i < 128 * 64; i += 256) {
        int k = i >> 6, j = i & 63;
        float v = W[i];
        int jt = j >> 3, c = j & 7;
        if (c < 4) wsa[k * 32 + jt * 4 + c] = v;
        else       wsb[k * 32 + jt * 4 + (c - 4)] = v;
    }
    int row0 = blockIdx.x * 256;
    int jt   = tid & 7;
    int rg8  = (tid >> 3) * 8;       // thread's first row (of 8)
    float acc[8][8];
#pragma unroll
    for (int i = 0; i < 8; i++)
#pragma unroll
        for (int j = 0; j < 8; j++) acc[i][j] = 0.f;

    int frow = tid >> 3;             // fill: row base 0..31
    int kq   = tid & 7;              // fill: k-quad
    int fsw  = kq << 2;              // fill swizzle (kk>>2 == kq for kk=kq*4+c)

    for (int kc = 0; kc < 4; kc++) {
        __syncthreads();
#pragma unroll
        for (int it = 0; it < 8; it++) {
            int row  = frow + it * 32;
            int grow = row0 + row;
            float4 v = (grow < n) ? *(const float4*)(x + (size_t)grow * 128 + kc * 32 + kq * 4)
                                  : make_float4(0.f, 0.f, 0.f, 0.f);
            int rs = row ^ fsw;
            xs[(kq * 4 + 0) * 256 + rs] = v.x;
            xs[(kq * 4 + 1) * 256 + rs] = v.y;
            xs[(kq * 4 + 2) * 256 + rs] = v.z;
            xs[(kq * 4 + 3) * 256 + rs] = v.w;
        }
        __syncthreads();
#pragma unroll
        for (int kk = 0; kk < 32; kk++) {
            int swz = ((kk >> 2) & 7) << 2;
            float4 x0 = *(const float4*)(xs + kk * 256 + (rg8 ^ swz));
            float4 x1 = *(const float4*)(xs + kk * 256 + ((rg8 + 4) ^ swz));
            int k = kc * 32 + kk;
            float4 a = *(const float4*)(wsa + k * 32 + jt * 4);
            float4 b = *(const float4*)(wsb + k * 32 + jt * 4);
            float xr[8] = {x0.x, x0.y, x0.z, x0.w, x1.x, x1.y, x1.z, x1.w};
#pragma unroll
            for (int i = 0; i < 8; i++) {
                acc[i][0] = fmaf(xr[i], a.x, acc[i][0]);
                acc[i][1] = fmaf(xr[i], a.y, acc[i][1]);
                acc[i][2] = fmaf(xr[i], a.z, acc[i][2]);
                acc[i][3] = fmaf(xr[i], a.w, acc[i][3]);
                acc[i][4] = fmaf(xr[i], b.x, acc[i][4]);
                acc[i][5] = fmaf(xr[i], b.y, acc[i][5]);
                acc[i][6] = fmaf(xr[i], b.z, acc[i][6]);
                acc[i][7] = fmaf(xr[i], b.w, acc[i][7]);
            }
        }
    }
#pragma unroll
    for (int i = 0; i < 8; i++) {
        int rr = row0 + rg8 + i;
        if (rr < n) {
            float di = g_dis[rr];
            __half2* o = g_h0h + (size_t)rr * 32 + jt * 4;
            o[0] = __floats2half2_rn(di*acc[i][0], di*acc[i][1]);
            o[1] = __floats2half2_rn(di*acc[i][2], di*acc[i][3]);
            o[2] = __floats2half2_rn(di*acc[i][4], di*acc[i][5]);
            o[3] = __floats2half2_rn(di*acc[i][6], di*acc[i][7]);
        }
    }
}

// ====== GEMM 2: g_ggh = fp16( dis[row] * (h[N,64] @ interleave(Wmu,Wls)) ) ======
__global__ void __launch_bounds__(256) gemm2_kernel(const float* __restrict__ Wmu,
                                                    const float* __restrict__ Wls, int n) {
    extern __shared__ float sm[];
    float* wsa = sm;
    float* wsb = sm + 2048;
    float* xs  = sm + 4096;
    int tid = threadIdx.x;
    for (int i = tid; i < 64 * 64; i += 256) {
        int k = i >> 6, j = i & 63;
        float v = (j < 32) ? Wmu[k * 32 + j] : Wls[k * 32 + (j - 32)];
        int jn = (j < 32) ? (2 * j) : (2 * (j - 32) + 1);   // interleave mu/ls
        int jt = jn >> 3, c = jn & 7;
        if (c < 4) wsa[k * 32 + jt * 4 + c] = v;
        else       wsb[k * 32 + jt * 4 + (c - 4)] = v;
    }
    int row0 = blockIdx.x * 256;
    int jt   = tid & 7;
    int rg8  = (tid >> 3) * 8;
    float acc[8][8];
#pragma unroll
    for (int i = 0; i < 8; i++)
#pragma unroll
        for (int j = 0; j < 8; j++) acc[i][j] = 0.f;

    int frow = tid >> 3;
    int kq   = tid & 7;
    int fsw  = kq << 2;

    for (int kc = 0; kc < 2; kc++) {
        __syncthreads();
#pragma unroll
        for (int it = 0; it < 8; it++) {
            int row  = frow + it * 32;
            int grow = row0 + row;
            float4 v = (grow < n) ? *(const float4*)(g_h + (size_t)grow * 64 + kc * 32 + kq * 4)
                                  : make_float4(0.f, 0.f, 0.f, 0.f);
            int rs = row ^ fsw;
            xs[(kq * 4 + 0) * 256 + rs] = v.x;
            xs[(kq * 4 + 1) * 256 + rs] = v.y;
            xs[(kq * 4 + 2) * 256 + rs] = v.z;
            xs[(kq * 4 + 3) * 256 + rs] = v.w;
        }
        __syncthreads();
#pragma unroll
        for (int kk = 0; kk < 32; kk++) {
            int swz = ((kk >> 2) & 7) << 2;
            float4 x0 = *(const float4*)(xs + kk * 256 + (rg8 ^ swz));
            float4 x1 = *(const float4*)(xs + kk * 256 + ((rg8 + 4) ^ swz));
            int k = kc * 32 + kk;
            float4 a = *(const float4*)(wsa + k * 32 + jt * 4);
            float4 b = *(const float4*)(wsb + k * 32 + jt * 4);
            float xr[8] = {x0.x, x0.y, x0.z, x0.w, x1.x, x1.y, x1.z, x1.w};
#pragma unroll
            for (int i = 0; i < 8; i++) {
                acc[i][0] = fmaf(xr[i], a.x, acc[i][0]);
                acc[i][1] = fmaf(xr[i], a.y, acc[i][1]);
                acc[i][2] = fmaf(xr[i], a.z, acc[i][2]);
                acc[i][3] = fmaf(xr[i], a.w, acc[i][3]);
                acc[i][4] = fmaf(xr[i], b.x, acc[i][4]);
                acc[i][5] = fmaf(xr[i], b.y, acc[i][5]);
                acc[i][6] = fmaf(xr[i], b.z, acc[i][6]);
                acc[i][7] = fmaf(xr[i], b.w, acc[i][7]);
            }
        }
    }
#pragma unroll
    for (int i = 0; i < 8; i++) {
        int rr = row0 + rg8 + i;
        if (rr < n) {
            float di = g_dis[rr];
            __half2* o = g_ggh + (size_t)rr * 32 + jt * 4;
            o[0] = __floats2half2_rn(di*acc[i][0], di*acc[i][1]);
            o[1] = __floats2half2_rn(di*acc[i][2], di*acc[i][3]);
            o[2] = __floats2half2_rn(di*acc[i][4], di*acc[i][5]);
            o[3] = __floats2half2_rn(di*acc[i][6], di*acc[i][7]);
        }
    }
}

// ---------------- Conv1: warp/node, fp16 gather, fp32 accumulate ----------------
__global__ void __launch_bounds__(256) conv1_kernel(const float* __restrict__ b1, int n) {
    int node = blockIdx.x * 8 + (threadIdx.x >> 5);
    int t    = threadIdx.x & 31;
    if (node >= n) return;
    int st  = g_rowstart[node];
    int cnt = g_indeg[node];
    const int* cs = g_csr + st;
    const __half2* hb = g_h0h + t;
    float a0x = 0.f, a0y = 0.f, a1x = 0.f, a1y = 0.f;
    int e = 0;
    for (; e + 8 <= cnt; e += 8) {
        int s0 = cs[e], s1 = cs[e+1], s2 = cs[e+2], s3 = cs[e+3];
        int s4 = cs[e+4], s5 = cs[e+5], s6 = cs[e+6], s7 = cs[e+7];
        float2 v0 = __half22float2(hb[(size_t)s0 * 32]);
        float2 v1 = __half22float2(hb[(size_t)s1 * 32]);
        float2 v2 = __half22float2(hb[(size_t)s2 * 32]);
        float2 v3 = __half22float2(hb[(size_t)s3 * 32]);
        float2 v4 = __half22float2(hb[(size_t)s4 * 32]);
        float2 v5 = __half22float2(hb[(size_t)s5 * 32]);
        float2 v6 = __half22float2(hb[(size_t)s6 * 32]);
        float2 v7 = __half22float2(hb[(size_t)s7 * 32]);
        a0x += v0.x; a0y += v0.y; a1x += v1.x; a1y += v1.y;
        a0x += v2.x; a0y += v2.y; a1x += v3.x; a1y += v3.y;
        a0x += v4.x; a0y += v4.y; a1x += v5.x; a1y += v5.y;
        a0x += v6.x; a0y += v6.y; a1x += v7.x; a1y += v7.y;
    }
    for (; e < cnt; e++) {
        float2 v = __half22float2(hb[(size_t)cs[e] * 32]);
        a0x += v.x; a0y += v.y;
    }
    float2 self = __half22float2(hb[(size_t)node * 32]);
    float sx = a0x + a1x + self.x;
    float sy = a0y + a1y + self.y;
    float di = g_dis[node];
    float2 bb = *(const float2*)(b1 + 2 * t);
    float vx = fmaxf(fmaf(di, sx, bb.x), 0.f);
    float vy = fmaxf(fmaf(di, sy, bb.y), 0.f);
    float ss = vx * vx + vy * vy;
#pragma unroll
    for (int o = 16; o > 0; o >>= 1) ss += __shfl_xor_sync(0xffffffffu, ss, o);
    float scale = 1.0f / fmaxf(sqrtf(ss), 1e-12f);
    *(float2*)(g_h + (size_t)node * 64 + 2 * t) = make_float2(vx * scale, vy * scale);
}

// ---------------- Conv2 + reparametrize ----------------
__global__ void __launch_bounds__(256) conv2_kernel(const float* __restrict__ bmu,
                                                    const float* __restrict__ bls,
                                                    const float* __restrict__ eps,
                                                    float* __restrict__ out_mu,
                                                    float* __restrict__ out_ls, int n) {
    int node = blockIdx.x * 8 + (threadIdx.x >> 5);
    int t    = threadIdx.x & 31;
    if (node >= n) return;
    int st  = g_rowstart[node];
    int cnt = g_indeg[node];
    const int* cs = g_csr + st;
    const __half2* gb = g_ggh + t;
    float a0x = 0.f, a0y = 0.f, a1x = 0.f, a1y = 0.f;
    int e = 0;
    for (; e + 8 <= cnt; e += 8) {
        int s0 = cs[e], s1 = cs[e+1], s2 = cs[e+2], s3 = cs[e+3];
        int s4 = cs[e+4], s5 = cs[e+5], s6 = cs[e+6], s7 = cs[e+7];
        float2 v0 = __half22float2(gb[(size_t)s0 * 32]);
        float2 v1 = __half22float2(gb[(size_t)s1 * 32]);
        float2 v2 = __half22float2(gb[(size_t)s2 * 32]);
        float2 v3 = __half22float2(gb[(size_t)s3 * 32]);
        float2 v4 = __half22float2(gb[(size_t)s4 * 32]);
        float2 v5 = __half22float2(gb[(size_t)s5 * 32]);
        float2 v6 = __half22float2(gb[(size_t)s6 * 32]);
        float2 v7 = __half22float2(gb[(size_t)s7 * 32]);
        a0x += v0.x; a0y += v0.y; a1x += v1.x; a1y += v1.y;
        a0x += v2.x; a0y += v2.y; a1x += v3.x; a1y += v3.y;
        a0x += v4.x; a0y += v4.y; a1x += v5.x; a1y += v5.y;
        a0x += v6.x; a0y += v6.y; a1x += v7.x; a1y += v7.y;
    }
    for (; e < cnt; e++) {
        float2 v = __half22float2(gb[(size_t)cs[e] * 32]);
        a0x += v.x; a0y += v.y;
    }
    float2 self = __half22float2(gb[(size_t)node * 32]);
    float sx = a0x + a1x + self.x;
    float sy = a0y + a1y + self.y;
    float di = g_dis[node];
    float mu = fmaf(di, sx, bmu[t]);
    float ls = fmaf(di, sy, bls[t]);
    size_t oi = (size_t)node * 32 + t;
    out_mu[oi] = mu;
    out_ls[oi] = ls;
    float lc = fminf(fmaxf(ls, -10.f), 10.f);
    g_zh[oi] = __float2half_rn(fmaf(eps[oi], __expf(lc), mu));
}

// ---------------- decode: 4 lanes/edge, uint4 (16B) loads ----------------
__global__ void __launch_bounds__(256) decode_kernel(const int* __restrict__ src,
                                                     const int* __restrict__ dst,
                                                     float* __restrict__ out, int E) {
    int gid = blockIdx.x * 256 + threadIdx.x;
    int e   = gid >> 2;
    int sub = gid & 3;
    if (e >= E) return;
    int s = src[e], d = dst[e];
    uint4 ua = *(const uint4*)(g_zh + (size_t)s * 32 + sub * 8);
    uint4 ub = *(const uint4*)(g_zh + (size_t)d * 32 + sub * 8);
    float2 a0 = __half22float2(*reinterpret_cast<__half2*>(&ua.x));
    float2 a1 = __half22float2(*reinterpret_cast<__half2*>(&ua.y));
    float2 a2 = __half22float2(*reinterpret_cast<__half2*>(&ua.z));
    float2 a3 = __half22float2(*reinterpret_cast<__half2*>(&ua.w));
    float2 b0 = __half22float2(*reinterpret_cast<__half2*>(&ub.x));
    float2 b1 = __half22float2(*reinterpret_cast<__half2*>(&ub.y));
    float2 b2 = __half22float2(*reinterpret_cast<__half2*>(&ub.z));
    float2 b3 = __half22float2(*reinterpret_cast<__half2*>(&ub.w));
    float p = a0.x*b0.x + a0.y*b0.y + a1.x*b1.x + a1.y*b1.y
            + a2.x*b2.x + a2.y*b2.y + a3.x*b3.x + a3.y*b3.y;
    p += __shfl_xor_sync(0xffffffffu, p, 1);
    p += __shfl_xor_sync(0xffffffffu, p, 2);
    if (sub == 0) out[e] = 1.0f / (1.0f + __expf(-p));
}

// ---------------- launch ----------------
extern "C" void kernel_launch(void* const* d_in, const int* in_sizes, int n_in,
                              void* d_out, int out_size) {
    const float* x   = (const float*)d_in[0];
    const int*   ei  = (const int*)  d_in[1];
    const float* eps = (const float*)d_in[2];
    const float* W1  = (const float*)d_in[3];
    const float* b1  = (const float*)d_in[4];
    const float* Wmu = (const float*)d_in[5];
    const float* bmu = (const float*)d_in[6];
    const float* Wls = (const float*)d_in[7];
    const float* bls = (const float*)d_in[8];

    int n = in_sizes[0] / 128;
    int E = in_sizes[1] / 2;
    const int* src = ei;
    const int* dst = ei + E;

    float* out     = (float*)d_out;
    float* out_adj = out;
    float* out_mu  = out + E;
    float* out_ls  = out + E + (size_t)n * 32;

    const int SMEM1 = (4096 + 4096 + 32 * 256) * 4;   // 65536
    const int SMEM2 = (2048 + 2048 + 32 * 256) * 4;   // 49152
    cudaFuncSetAttribute(gemm1_kernel, cudaFuncAttributeMaxDynamicSharedMemorySize, SMEM1);
    cudaFuncSetAttribute(gemm2_kernel, cudaFuncAttributeMaxDynamicSharedMemorySize, SMEM2);

    cudaStream_t s2;
    cudaEvent_t evFork, evJoin;
    cudaStreamCreateWithFlags(&s2, cudaStreamNonBlocking);
    cudaEventCreateWithFlags(&evFork, cudaEventDisableTiming);
    cudaEventCreateWithFlags(&evJoin, cudaEventDisableTiming);

    init_kernel<<<(n + 255) / 256, 256>>>(n);
    hist_kernel<<<(E + 255) / 256, 256>>>(dst, E);
    dis_kernel<<<(n + 255) / 256, 256>>>(n);

    // fork: gemm1 depends only on {x, W1, dis}
    cudaEventRecord(evFork, 0);
    cudaStreamWaitEvent(s2, evFork, 0);
    gemm1_kernel<<<(n + 255) / 256, 256, SMEM1, s2>>>(x, W1, n);
    cudaEventRecord(evJoin, s2);

    int nb = (n + 1023) / 1024;
    scan1_kernel<<<nb, 1024>>>(n);
    scan2_kernel<<<1, 256>>>(nb);
    scan3_kernel<<<(n + 255) / 256, 256>>>(n);
    fill_kernel<<<(E + 255) / 256, 256>>>(src, dst, E);

    cudaStreamWaitEvent(0, evJoin, 0);

    conv1_kernel<<<(n + 7) / 8, 256>>>(b1, n);
    gemm2_kernel<<<(n + 255) / 256, 256, SMEM2>>>(Wmu, Wls, n);
    conv2_kernel<<<(n + 7) / 8, 256>>>(bmu, bls, eps, out_mu, out_ls, n);
    decode_kernel<<<((size_t)E * 4 + 255) / 256, 256>>>(src, dst, out_adj, E);
}

// round 10
// speedup vs baseline: 2.3496x; 1.0582x over previous
#include <cuda_runtime.h>
#include <cuda_fp16.h>
#include <math.h>

#define MAXN 100000
#define MAXE 1600000

// ---------------- scratch ----------------
__device__ int     g_indeg[MAXN];
__device__ int     g_rowstart[MAXN];
__device__ int     g_cursor[MAXN];
__device__ int     g_bsum[256];
__device__ float   g_dis[MAXN];
__device__ int     g_csr[MAXE];
__device__ __half2 g_h0h[(size_t)MAXN * 32];    // fp16 dis-prescaled x@W1
__device__ float   g_h [(size_t)MAXN * 64];     // fp32 normalized hidden
__device__ __half2 g_ggh[(size_t)MAXN * 32];    // fp16 dis-prescaled (mu,ls) interleaved
__device__ __half  g_zh [(size_t)MAXN * 32];    // fp16 z

// ---------------- graph preprocessing ----------------
__global__ void init_kernel(int n) {
    int i = blockIdx.x * blockDim.x + threadIdx.x;
    if (i < n) g_indeg[i] = 0;
}

__global__ void hist_kernel(const int* __restrict__ dst, int E) {
    int e = blockIdx.x * blockDim.x + threadIdx.x;
    if (e < E) atomicAdd(&g_indeg[dst[e]], 1);
}

__global__ void dis_kernel(int n) {
    int i = blockIdx.x * blockDim.x + threadIdx.x;
    if (i < n) g_dis[i] = rsqrtf((float)(g_indeg[i] + 1));
}

__global__ void scan1_kernel(int n) {
    __shared__ int sm[1024];
    int t = threadIdx.x;
    int i = blockIdx.x * 1024 + t;
    int v = (i < n) ? g_indeg[i] : 0;
    sm[t] = v;
    __syncthreads();
#pragma unroll
    for (int o = 1; o < 1024; o <<= 1) {
        int tv = (t >= o) ? sm[t - o] : 0;
        __syncthreads();
        sm[t] += tv;
        __syncthreads();
    }
    if (i < n) g_rowstart[i] = sm[t] - v;
    if (t == 1023) g_bsum[blockIdx.x] = sm[1023];
}

__global__ void scan2_kernel(int nb) {
    __shared__ int sm[256];
    int t = threadIdx.x;
    int v = (t < nb) ? g_bsum[t] : 0;
    sm[t] = v;
    __syncthreads();
#pragma unroll
    for (int o = 1; o < 256; o <<= 1) {
        int tv = (t >= o) ? sm[t - o] : 0;
        __syncthreads();
        sm[t] += tv;
        __syncthreads();
    }
    if (t < nb) g_bsum[t] = sm[t] - v;
}

__global__ void scan3_kernel(int n) {
    int i = blockIdx.x * blockDim.x + threadIdx.x;
    if (i < n) {
        int v = g_rowstart[i] + g_bsum[i >> 10];
        g_rowstart[i] = v;
        g_cursor[i]   = v;
    }
}

__global__ void fill_kernel(const int* __restrict__ src, const int* __restrict__ dst, int E) {
    int e = blockIdx.x * blockDim.x + threadIdx.x;
    if (e < E) {
        int p = atomicAdd(&g_cursor[dst[e]], 1);
        g_csr[p] = src[e];
    }
}

// ============ GEMM 1 (R7 config): 128 rows/block, thread = 4 rows x 8 cols ============
__global__ void __launch_bounds__(256) gemm1_kernel(const float* __restrict__ x,
                                                    const float* __restrict__ W, int n) {
    extern __shared__ float sm[];
    float* wsa = sm;            // cols jt*8..+3  at [k*32 + jt*4]
    float* wsb = sm + 4096;     // cols jt*8+4..+7
    float* xs  = sm + 8192;     // [kk][row^swz], stride 132
    int tid = threadIdx.x;
    for (int i = tid; i < 128 * 64; i += 256) {
        int k = i >> 6, j = i & 63;
        float v = W[i];
        int jt = j >> 3, c = j & 7;
        if (c < 4) wsa[k * 32 + jt * 4 + c] = v;
        else       wsb[k * 32 + jt * 4 + (c - 4)] = v;
    }
    int row0 = blockIdx.x * 128;
    int lane = tid & 31, wrp = tid >> 5;
    int rg4 = (wrp * 4 + (lane >> 3)) * 4;   // thread's first row (of 4)
    int jt  = lane & 7;
    float acc[4][8];
#pragma unroll
    for (int i = 0; i < 4; i++)
#pragma unroll
        for (int j = 0; j < 8; j++) acc[i][j] = 0.f;

    int frow = tid >> 3;                     // fill: row base 0..31
    int kq   = tid & 7;                      // fill: k-quad 0..7
    int csw  = ((kq & 3) << 3) | ((kq >> 2) << 2);   // swizzle

    for (int kc = 0; kc < 4; kc++) {
        __syncthreads();
#pragma unroll
        for (int it = 0; it < 4; it++) {
            int row  = frow + it * 32;
            int grow = row0 + row;
            float4 v = (grow < n) ? *(const float4*)(x + (size_t)grow * 128 + kc * 32 + kq * 4)
                                  : make_float4(0.f, 0.f, 0.f, 0.f);
            int rs = row ^ csw;
            xs[(kq * 4 + 0) * 132 + rs] = v.x;
            xs[(kq * 4 + 1) * 132 + rs] = v.y;
            xs[(kq * 4 + 2) * 132 + rs] = v.z;
            xs[(kq * 4 + 3) * 132 + rs] = v.w;
        }
        __syncthreads();
#pragma unroll
        for (int kk = 0; kk < 32; kk++) {
            int c = (((kk >> 2) & 3) << 3) | (((kk >> 4) & 1) << 2);
            float4 xv = *(const float4*)(xs + kk * 132 + (rg4 ^ c));
            int k = kc * 32 + kk;
            float4 a = *(const float4*)(wsa + k * 32 + jt * 4);
            float4 b = *(const float4*)(wsb + k * 32 + jt * 4);
            float xr[4] = {xv.x, xv.y, xv.z, xv.w};
#pragma unroll
            for (int i = 0; i < 4; i++) {
                acc[i][0] = fmaf(xr[i], a.x, acc[i][0]);
                acc[i][1] = fmaf(xr[i], a.y, acc[i][1]);
                acc[i][2] = fmaf(xr[i], a.z, acc[i][2]);
                acc[i][3] = fmaf(xr[i], a.w, acc[i][3]);
                acc[i][4] = fmaf(xr[i], b.x, acc[i][4]);
                acc[i][5] = fmaf(xr[i], b.y, acc[i][5]);
                acc[i][6] = fmaf(xr[i], b.z, acc[i][6]);
                acc[i][7] = fmaf(xr[i], b.w, acc[i][7]);
            }
        }
    }
#pragma unroll
    for (int i = 0; i < 4; i++) {
        int rr = row0 + rg4 + i;
        if (rr < n) {
            float di = g_dis[rr];
            __half2* o = g_h0h + (size_t)rr * 32 + jt * 4;
            o[0] = __floats2half2_rn(di*acc[i][0], di*acc[i][1]);
            o[1] = __floats2half2_rn(di*acc[i][2], di*acc[i][3]);
            o[2] = __floats2half2_rn(di*acc[i][4], di*acc[i][5]);
            o[3] = __floats2half2_rn(di*acc[i][6], di*acc[i][7]);
        }
    }
}

// ====== GEMM 2 (R7 config): 128 rows/block, thread = 4 rows x 8 cols ======
__global__ void __launch_bounds__(256) gemm2_kernel(const float* __restrict__ Wmu,
                                                    const float* __restrict__ Wls, int n) {
    extern __shared__ float sm[];
    float* wsa = sm;
    float* wsb = sm + 2048;
    float* xs  = sm + 4096;
    int tid = threadIdx.x;
    for (int i = tid; i < 64 * 64; i += 256) {
        int k = i >> 6, j = i & 63;
        float v = (j < 32) ? Wmu[k * 32 + j] : Wls[k * 32 + (j - 32)];
        int jn = (j < 32) ? (2 * j) : (2 * (j - 32) + 1);   // interleave mu/ls
        int jt = jn >> 3, c = jn & 7;
        if (c < 4) wsa[k * 32 + jt * 4 + c] = v;
        else       wsb[k * 32 + jt * 4 + (c - 4)] = v;
    }
    int row0 = blockIdx.x * 128;
    int lane = tid & 31, wrp = tid >> 5;
    int rg4 = (wrp * 4 + (lane >> 3)) * 4;
    int jt  = lane & 7;
    float acc[4][8];
#pragma unroll
    for (int i = 0; i < 4; i++)
#pragma unroll
        for (int j = 0; j < 8; j++) acc[i][j] = 0.f;

    int frow = tid >> 3;
    int kq   = tid & 7;
    int csw  = ((kq & 3) << 3) | ((kq >> 2) << 2);

    for (int kc = 0; kc < 2; kc++) {
        __syncthreads();
#pragma unroll
        for (int it = 0; it < 4; it++) {
            int row  = frow + it * 32;
            int grow = row0 + row;
            float4 v = (grow < n) ? *(const float4*)(g_h + (size_t)grow * 64 + kc * 32 + kq * 4)
                                  : make_float4(0.f, 0.f, 0.f, 0.f);
            int rs = row ^ csw;
            xs[(kq * 4 + 0) * 132 + rs] = v.x;
            xs[(kq * 4 + 1) * 132 + rs] = v.y;
            xs[(kq * 4 + 2) * 132 + rs] = v.z;
            xs[(kq * 4 + 3) * 132 + rs] = v.w;
        }
        __syncthreads();
#pragma unroll
        for (int kk = 0; kk < 32; kk++) {
            int c = (((kk >> 2) & 3) << 3) | (((kk >> 4) & 1) << 2);
            float4 xv = *(const float4*)(xs + kk * 132 + (rg4 ^ c));
            int k = kc * 32 + kk;
            float4 a = *(const float4*)(wsa + k * 32 + jt * 4);
            float4 b = *(const float4*)(wsb + k * 32 + jt * 4);
            float xr[4] = {xv.x, xv.y, xv.z, xv.w};
#pragma unroll
            for (int i = 0; i < 4; i++) {
                acc[i][0] = fmaf(xr[i], a.x, acc[i][0]);
                acc[i][1] = fmaf(xr[i], a.y, acc[i][1]);
                acc[i][2] = fmaf(xr[i], a.z, acc[i][2]);
                acc[i][3] = fmaf(xr[i], a.w, acc[i][3]);
                acc[i][4] = fmaf(xr[i], b.x, acc[i][4]);
                acc[i][5] = fmaf(xr[i], b.y, acc[i][5]);
                acc[i][6] = fmaf(xr[i], b.z, acc[i][6]);
                acc[i][7] = fmaf(xr[i], b.w, acc[i][7]);
            }
        }
    }
#pragma unroll
    for (int i = 0; i < 4; i++) {
        int rr = row0 + rg4 + i;
        if (rr < n) {
            float di = g_dis[rr];
            __half2* o = g_ggh + (size_t)rr * 32 + jt * 4;
            o[0] = __floats2half2_rn(di*acc[i][0], di*acc[i][1]);
            o[1] = __floats2half2_rn(di*acc[i][2], di*acc[i][3]);
            o[2] = __floats2half2_rn(di*acc[i][4], di*acc[i][5]);
            o[3] = __floats2half2_rn(di*acc[i][6], di*acc[i][7]);
        }
    }
}

// ---------------- Conv1: warp/node, fp16 gather, fp32 accumulate ----------------
__global__ void __launch_bounds__(256) conv1_kernel(const float* __restrict__ b1, int n) {
    int node = blockIdx.x * 8 + (threadIdx.x >> 5);
    int t    = threadIdx.x & 31;
    if (node >= n) return;
    int st  = g_rowstart[node];
    int cnt = g_indeg[node];
    const int* cs = g_csr + st;
    const __half2* hb = g_h0h + t;
    float a0x = 0.f, a0y = 0.f, a1x = 0.f, a1y = 0.f;
    int e = 0;
    for (; e + 8 <= cnt; e += 8) {
        int s0 = cs[e], s1 = cs[e+1], s2 = cs[e+2], s3 = cs[e+3];
        int s4 = cs[e+4], s5 = cs[e+5], s6 = cs[e+6], s7 = cs[e+7];
        float2 v0 = __half22float2(hb[(size_t)s0 * 32]);
        float2 v1 = __half22float2(hb[(size_t)s1 * 32]);
        float2 v2 = __half22float2(hb[(size_t)s2 * 32]);
        float2 v3 = __half22float2(hb[(size_t)s3 * 32]);
        float2 v4 = __half22float2(hb[(size_t)s4 * 32]);
        float2 v5 = __half22float2(hb[(size_t)s5 * 32]);
        float2 v6 = __half22float2(hb[(size_t)s6 * 32]);
        float2 v7 = __half22float2(hb[(size_t)s7 * 32]);
        a0x += v0.x; a0y += v0.y; a1x += v1.x; a1y += v1.y;
        a0x += v2.x; a0y += v2.y; a1x += v3.x; a1y += v3.y;
        a0x += v4.x; a0y += v4.y; a1x += v5.x; a1y += v5.y;
        a0x += v6.x; a0y += v6.y; a1x += v7.x; a1y += v7.y;
    }
    for (; e < cnt; e++) {
        float2 v = __half22float2(hb[(size_t)cs[e] * 32]);
        a0x += v.x; a0y += v.y;
    }
    float2 self = __half22float2(hb[(size_t)node * 32]);
    float sx = a0x + a1x + self.x;
    float sy = a0y + a1y + self.y;
    float di = g_dis[node];
    float2 bb = *(const float2*)(b1 + 2 * t);
    float vx = fmaxf(fmaf(di, sx, bb.x), 0.f);
    float vy = fmaxf(fmaf(di, sy, bb.y), 0.f);
    float ss = vx * vx + vy * vy;
#pragma unroll
    for (int o = 16; o > 0; o >>= 1) ss += __shfl_xor_sync(0xffffffffu, ss, o);
    float scale = 1.0f / fmaxf(sqrtf(ss), 1e-12f);
    *(float2*)(g_h + (size_t)node * 64 + 2 * t) = make_float2(vx * scale, vy * scale);
}

// ---------------- Conv2 + reparametrize ----------------
__global__ void __launch_bounds__(256) conv2_kernel(const float* __restrict__ bmu,
                                                    const float* __restrict__ bls,
                                                    const float* __restrict__ eps,
                                                    float* __restrict__ out_mu,
                                                    float* __restrict__ out_ls, int n) {
    int node = blockIdx.x * 8 + (threadIdx.x >> 5);
    int t    = threadIdx.x & 31;
    if (node >= n) return;
    int st  = g_rowstart[node];
    int cnt = g_indeg[node];
    const int* cs = g_csr + st;
    const __half2* gb = g_ggh + t;
    float a0x = 0.f, a0y = 0.f, a1x = 0.f, a1y = 0.f;
    int e = 0;
    for (; e + 8 <= cnt; e += 8) {
        int s0 = cs[e], s1 = cs[e+1], s2 = cs[e+2], s3 = cs[e+3];
        int s4 = cs[e+4], s5 = cs[e+5], s6 = cs[e+6], s7 = cs[e+7];
        float2 v0 = __half22float2(gb[(size_t)s0 * 32]);
        float2 v1 = __half22float2(gb[(size_t)s1 * 32]);
        float2 v2 = __half22float2(gb[(size_t)s2 * 32]);
        float2 v3 = __half22float2(gb[(size_t)s3 * 32]);
        float2 v4 = __half22float2(gb[(size_t)s4 * 32]);
        float2 v5 = __half22float2(gb[(size_t)s5 * 32]);
        float2 v6 = __half22float2(gb[(size_t)s6 * 32]);
        float2 v7 = __half22float2(gb[(size_t)s7 * 32]);
        a0x += v0.x; a0y += v0.y; a1x += v1.x; a1y += v1.y;
        a0x += v2.x; a0y += v2.y; a1x += v3.x; a1y += v3.y;
        a0x += v4.x; a0y += v4.y; a1x += v5.x; a1y += v5.y;
        a0x += v6.x; a0y += v6.y; a1x += v7.x; a1y += v7.y;
    }
    for (; e < cnt; e++) {
        float2 v = __half22float2(gb[(size_t)cs[e] * 32]);
        a0x += v.x; a0y += v.y;
    }
    float2 self = __half22float2(gb[(size_t)node * 32]);
    float sx = a0x + a1x + self.x;
    float sy = a0y + a1y + self.y;
    float di = g_dis[node];
    float mu = fmaf(di, sx, bmu[t]);
    float ls = fmaf(di, sy, bls[t]);
    size_t oi = (size_t)node * 32 + t;
    out_mu[oi] = mu;
    out_ls[oi] = ls;
    float lc = fminf(fmaxf(ls, -10.f), 10.f);
    g_zh[oi] = __float2half_rn(fmaf(eps[oi], __expf(lc), mu));
}

// ---------------- decode: 4 lanes/edge, uint4 (16B) loads ----------------
__global__ void __launch_bounds__(256) decode_kernel(const int* __restrict__ src,
                                                     const int* __restrict__ dst,
                                                     float* __restrict__ out, int E) {
    int gid = blockIdx.x * 256 + threadIdx.x;
    int e   = gid >> 2;
    int sub = gid & 3;
    if (e >= E) return;
    int s = src[e], d = dst[e];
    uint4 ua = *(const uint4*)(g_zh + (size_t)s * 32 + sub * 8);
    uint4 ub = *(const uint4*)(g_zh + (size_t)d * 32 + sub * 8);
    float2 a0 = __half22float2(*reinterpret_cast<__half2*>(&ua.x));
    float2 a1 = __half22float2(*reinterpret_cast<__half2*>(&ua.y));
    float2 a2 = __half22float2(*reinterpret_cast<__half2*>(&ua.z));
    float2 a3 = __half22float2(*reinterpret_cast<__half2*>(&ua.w));
    float2 b0 = __half22float2(*reinterpret_cast<__half2*>(&ub.x));
    float2 b1 = __half22float2(*reinterpret_cast<__half2*>(&ub.y));
    float2 b2 = __half22float2(*reinterpret_cast<__half2*>(&ub.z));
    float2 b3 = __half22float2(*reinterpret_cast<__half2*>(&ub.w));
    float p = a0.x*b0.x + a0.y*b0.y + a1.x*b1.x + a1.y*b1.y
            + a2.x*b2.x + a2.y*b2.y + a3.x*b3.x + a3.y*b3.y;
    p += __shfl_xor_sync(0xffffffffu, p, 1);
    p += __shfl_xor_sync(0xffffffffu, p, 2);
    if (sub == 0) out[e] = 1.0f / (1.0f + __expf(-p));
}

// ---------------- launch ----------------
extern "C" void kernel_launch(void* const* d_in, const int* in_sizes, int n_in,
                              void* d_out, int out_size) {
    const float* x   = (const float*)d_in[0];
    const int*   ei  = (const int*)  d_in[1];
    const float* eps = (const float*)d_in[2];
    const float* W1  = (const float*)d_in[3];
    const float* b1  = (const float*)d_in[4];
    const float* Wmu = (const float*)d_in[5];
    const float* bmu = (const float*)d_in[6];
    const float* Wls = (const float*)d_in[7];
    const float* bls = (const float*)d_in[8];

    int n = in_sizes[0] / 128;
    int E = in_sizes[1] / 2;
    const int* src = ei;
    const int* dst = ei + E;

    float* out     = (float*)d_out;
    float* out_adj = out;
    float* out_mu  = out + E;
    float* out_ls  = out + E + (size_t)n * 32;

    const int SMEM1 = (4096 + 4096 + 32 * 132) * 4;   // 49664
    const int SMEM2 = (2048 + 2048 + 32 * 132) * 4;   // 33280
    cudaFuncSetAttribute(gemm1_kernel, cudaFuncAttributeMaxDynamicSharedMemorySize, SMEM1);
    cudaFuncSetAttribute(gemm2_kernel, cudaFuncAttributeMaxDynamicSharedMemorySize, SMEM2);

    cudaStream_t s2;
    cudaEvent_t evFork, evJoin;
    cudaStreamCreateWithFlags(&s2, cudaStreamNonBlocking);
    cudaEventCreateWithFlags(&evFork, cudaEventDisableTiming);
    cudaEventCreateWithFlags(&evJoin, cudaEventDisableTiming);

    init_kernel<<<(n + 255) / 256, 256>>>(n);
    hist_kernel<<<(E + 255) / 256, 256>>>(dst, E);
    dis_kernel<<<(n + 255) / 256, 256>>>(n);

    // fork: gemm1 depends only on {x, W1, dis}
    cudaEventRecord(evFork, 0);
    cudaStreamWaitEvent(s2, evFork, 0);
    gemm1_kernel<<<(n + 127) / 128, 256, SMEM1, s2>>>(x, W1, n);
    cudaEventRecord(evJoin, s2);

    int nb = (n + 1023) / 1024;
    scan1_kernel<<<nb, 1024>>>(n);
    scan2_kernel<<<1, 256>>>(nb);
    scan3_kernel<<<(n + 255) / 256, 256>>>(n);
    fill_kernel<<<(E + 255) / 256, 256>>>(src, dst, E);

    cudaStreamWaitEvent(0, evJoin, 0);

    conv1_kernel<<<(n + 7) / 8, 256>>>(b1, n);
    gemm2_kernel<<<(n + 127) / 128, 256, SMEM2>>>(Wmu, Wls, n);
    conv2_kernel<<<(n + 7) / 8, 256>>>(bmu, bls, eps, out_mu, out_ls, n);
    decode_kernel<<<((size_t)E * 4 + 255) / 256, 256>>>(src, dst, out_adj, E);
}